// round 1
// baseline (speedup 1.0000x reference)
#include <cuda_runtime.h>
#include <math.h>
#include <stdint.h>

// Problem constants (fixed shapes)
#define Bz   32
#define TTz  64
#define TSz  128
#define ENCz 512
#define Ez   512
#define Hz   1024
#define Lz   4
#define Vz   32000
#define Dz   1024
#define G4   4096   // 4*H

// ---------------- scratch (device globals; no allocation allowed) ----------------
__device__ float g_kproj [Bz*TSz*Dz];    // [ (b*TS+s), d ]  enc_out @ Wk^T
__device__ float g_M2    [Bz*TSz*Hz];    // [ (b*TS+s), h ]  kproj @ Wq
__device__ float g_WqT   [Hz*Dz];        // [h, d] = Wq[d, h]
__device__ float g_embA  [TTz*Bz*Ez];    // [ (t*B+b), e ] gathered embeddings
__device__ float g_embih [TTz*Bz*G4];    // [ (t*B+b), r'] emb @ wpih0[:, :512]^T + bias0
__device__ float g_wpih  [Lz*G4*Hz];     // gate-interleaved w_ih  (row r' = 4j+g)
__device__ float g_wphh  [Lz*G4*Hz];     // gate-interleaved w_hh
__device__ float g_pbias [Lz*G4];        // permuted b_ih + b_hh
__device__ float g_h     [Lz*Bz*Hz];
__device__ float g_c     [Lz*Bz*Hz];
__device__ float g_x     [Bz*Hz];        // current layer-stack output (with residual)
__device__ float g_stepin[Bz*Hz];        // [emb_t | ctx]
__device__ float g_xstore[Bz*TTz*Hz];    // [ (b*TT+t), h ] final x per step (proj input)

// ---------------- prologue: permute/gather/transpose/init ----------------
__global__ void prep_kernel(const int* __restrict__ tgt,
                            const float* __restrict__ embedding,
                            const float* __restrict__ w_ih,
                            const float* __restrict__ w_hh,
                            const float* __restrict__ b_ih,
                            const float* __restrict__ b_hh,
                            const float* __restrict__ Wq)
{
    const int stride = gridDim.x * blockDim.x;
    const int base   = blockIdx.x * blockDim.x + threadIdx.x;

    // 1) gate-interleave weights: dst row r' = 4j+g <- src row g*1024+j
    for (int i = base; i < Lz*G4*Hz; i += stride) {
        int k  = i & (Hz-1);
        int rp = (i >> 10) & (G4-1);
        int l  = i >> 22;              // i / (G4*Hz) with G4*Hz = 2^22
        int j  = rp >> 2;
        int g  = rp & 3;
        int src = (l*G4 + g*Hz + j)*Hz + k;
        g_wpih[i] = w_ih[src];
        g_wphh[i] = w_hh[src];
    }
    // 2) permuted combined bias
    for (int i = base; i < Lz*G4; i += stride) {
        int rp = i & (G4-1);
        int l  = i >> 12;
        int j  = rp >> 2, g = rp & 3;
        g_pbias[i] = b_ih[l*G4 + g*Hz + j] + b_hh[l*G4 + g*Hz + j];
    }
    // 3) embedding gather: row m = t*B + b
    for (int i = base; i < TTz*Bz*Ez; i += stride) {
        int e = i & (Ez-1);
        int m = i >> 9;
        int t = m / Bz, b = m % Bz;
        int tok = tgt[b*TTz + t];
        g_embA[i] = embedding[(size_t)tok*Ez + e];
    }
    // 4) Wq transpose: WqT[h][d] = Wq[d][h]
    for (int i = base; i < Hz*Dz; i += stride) {
        int d = i & (Dz-1);
        int h = i >> 10;
        g_WqT[i] = Wq[d*Hz + h];
    }
    // 5) zero states
    for (int i = base; i < Lz*Bz*Hz; i += stride) { g_h[i] = 0.f; g_c[i] = 0.f; }
    // 6) stepin for t=0: [emb(tgt[:,0]) | 0]
    for (int i = base; i < Bz*Hz; i += stride) {
        int p = i & (Hz-1);
        int b = i >> 10;
        g_stepin[i] = (p < Ez) ? embedding[(size_t)tgt[b*TTz + 0]*Ez + p] : 0.f;
    }
}

// ---------------- generic NT GEMM: C[m,n] = sum_k A[m,k]*B[n,k] (+bias[n]) ------
// A: row-major, lda; B: row-major (K contiguous), ldb. M = gridDim.y*BM, N = gridDim.x*BN.
// Requires: M%BM==0, N%BN==0, K%16==0, rows 16B-aligned.
template<int BM, int BN, int TM, int TN>
__global__ void gemm_nt_kernel(const float* __restrict__ A, int lda,
                               const float* __restrict__ Bm, int ldb,
                               float* __restrict__ C, int ldc,
                               int K, const float* __restrict__ bias)
{
    constexpr int NT = (BM/TM)*(BN/TN);
    constexpr int KC = 16;
    __shared__ float As[KC][BM];
    __shared__ float Bs[KC][BN];
    const int m0  = blockIdx.y * BM;
    const int n0  = blockIdx.x * BN;
    const int tid = threadIdx.x;
    const int tx  = tid % (BN/TN);
    const int ty  = tid / (BN/TN);

    float acc[TM][TN];
#pragma unroll
    for (int i = 0; i < TM; ++i)
#pragma unroll
        for (int j = 0; j < TN; ++j) acc[i][j] = 0.f;

    for (int k0 = 0; k0 < K; k0 += KC) {
        __syncthreads();
#pragma unroll
        for (int it = 0; it < (BM*KC/4)/NT; ++it) {
            int idx = tid + it*NT;
            int m = idx >> 2, k4 = (idx & 3) * 4;
            float4 v = *(const float4*)&A[(size_t)(m0+m)*lda + k0 + k4];
            As[k4+0][m] = v.x; As[k4+1][m] = v.y; As[k4+2][m] = v.z; As[k4+3][m] = v.w;
        }
#pragma unroll
        for (int it = 0; it < (BN*KC/4)/NT; ++it) {
            int idx = tid + it*NT;
            int n = idx >> 2, k4 = (idx & 3) * 4;
            float4 v = *(const float4*)&Bm[(size_t)(n0+n)*ldb + k0 + k4];
            Bs[k4+0][n] = v.x; Bs[k4+1][n] = v.y; Bs[k4+2][n] = v.z; Bs[k4+3][n] = v.w;
        }
        __syncthreads();
#pragma unroll
        for (int kk = 0; kk < KC; ++kk) {
            float a[TM], b[TN];
#pragma unroll
            for (int i = 0; i < TM; ++i) a[i] = As[kk][ty*TM + i];
#pragma unroll
            for (int j = 0; j < TN; ++j) b[j] = Bs[kk][tx*TN + j];
#pragma unroll
            for (int i = 0; i < TM; ++i)
#pragma unroll
                for (int j = 0; j < TN; ++j) acc[i][j] += a[i]*b[j];
        }
    }
#pragma unroll
    for (int i = 0; i < TM; ++i) {
        int m = m0 + ty*TM + i;
#pragma unroll
        for (int j = 0; j < TN; ++j) {
            int n = n0 + tx*TN + j;
            float v = acc[i][j];
            if (bias) v += bias[n];
            C[(size_t)m*ldc + n] = v;
        }
    }
}

// ---------------- fused LSTM layer: gates GEMM + cell epilogue ----------------
// Weights are gate-interleaved (r' = 4j+g), so each thread's 4 consecutive
// accumulator columns are (i,f,g,o) for one hidden unit j.
// grid = 64 blocks (G4/64), 128 threads. Block tile: 32 b x 64 r'. Micro 4x4.
__global__ void lstm_layer_kernel(int l, int t)
{
    __shared__ float As[16][32];
    __shared__ float Ws[16][64];
    const int tid = threadIdx.x;
    const int n0  = blockIdx.x * 64;
    const int tx  = tid & 15;       // 16 column-threads (4 r' each)
    const int ty  = tid >> 4;       // 8 row-threads (4 b each)

    float acc[4][4];
#pragma unroll
    for (int i = 0; i < 4; ++i)
#pragma unroll
        for (int j = 0; j < 4; ++j) acc[i][j] = 0.f;

    for (int seg = 0; seg < 2; ++seg) {
        const float* Ap; const float* Wp; int Ksz;
        if (seg == 0) {
            if (l == 0) { Ap = g_stepin + Ez; Wp = g_wpih + Ez; Ksz = Ez; }           // ctx part
            else        { Ap = g_x;           Wp = g_wpih + (size_t)l*G4*Hz; Ksz = Hz; }
        } else          { Ap = g_h + (size_t)l*Bz*Hz; Wp = g_wphh + (size_t)l*G4*Hz; Ksz = Hz; }

        for (int k0 = 0; k0 < Ksz; k0 += 16) {
            __syncthreads();
            {   // A tile 32x16 : 128 float4, one per thread
                int m = tid >> 2, k4 = (tid & 3) * 4;
                float4 v = *(const float4*)&Ap[(size_t)m*Hz + k0 + k4];
                As[k4+0][m] = v.x; As[k4+1][m] = v.y; As[k4+2][m] = v.z; As[k4+3][m] = v.w;
            }
#pragma unroll
            for (int it = 0; it < 2; ++it) { // W tile 64x16 : 256 float4
                int idx = tid + it*128;
                int n = idx >> 2, k4 = (idx & 3) * 4;
                float4 v = *(const float4*)&Wp[(size_t)(n0+n)*Hz + k0 + k4];
                Ws[k4+0][n] = v.x; Ws[k4+1][n] = v.y; Ws[k4+2][n] = v.z; Ws[k4+3][n] = v.w;
            }
            __syncthreads();
#pragma unroll
            for (int kk = 0; kk < 16; ++kk) {
                float a[4], w[4];
#pragma unroll
                for (int i = 0; i < 4; ++i) a[i] = As[kk][ty*4 + i];
#pragma unroll
                for (int j = 0; j < 4; ++j) w[j] = Ws[kk][tx*4 + j];
#pragma unroll
                for (int i = 0; i < 4; ++i)
#pragma unroll
                    for (int j = 0; j < 4; ++j) acc[i][j] += a[i]*w[j];
            }
        }
    }

    // cell epilogue: r' base = n0 + tx*4 (multiple of 4) -> j = base/4, g = 0..3
    const int rbase = n0 + tx*4;
    const int j = rbase >> 2;
#pragma unroll
    for (int i = 0; i < 4; ++i) {
        const int b = ty*4 + i;
        float iv, fv, gv, ov;
        if (l == 0) {
            const float* e = &g_embih[((size_t)t*Bz + b)*G4 + rbase];
            iv = acc[i][0] + e[0]; fv = acc[i][1] + e[1];
            gv = acc[i][2] + e[2]; ov = acc[i][3] + e[3];
        } else {
            const float* pb = &g_pbias[l*G4 + rbase];
            iv = acc[i][0] + pb[0]; fv = acc[i][1] + pb[1];
            gv = acc[i][2] + pb[2]; ov = acc[i][3] + pb[3];
        }
        float ig = 1.f/(1.f + expf(-iv));
        float fg = 1.f/(1.f + expf(-fv));
        float gg = tanhf(gv);
        float og = 1.f/(1.f + expf(-ov));
        const int ci = (l*Bz + b)*Hz + j;
        float c2 = fg * g_c[ci] + ig * gg;
        g_c[ci] = c2;
        float h2 = og * tanhf(c2);
        g_h[ci] = h2;
        float x = h2 + ((l >= 2) ? g_stepin[b*Hz + j] : 0.f);
        g_x[b*Hz + j] = x;
        if (l == 3) g_xstore[((size_t)b*TTz + t)*Hz + j] = x;
    }
}

// ---------------- attention + next-step input (one block per batch) ----------------
__global__ void attn_kernel(int t,
                            const int*   __restrict__ enc_mask,
                            const float* __restrict__ enc_out)
{
    const int b   = blockIdx.x;
    const int tid = threadIdx.x;   // 256
    __shared__ float xs[Hz];
    __shared__ float sc[TSz];
    __shared__ float red[8];

    for (int i = tid; i < Hz; i += 256) xs[i] = g_x[b*Hz + i];
    __syncthreads();

    const int warp = tid >> 5, lane = tid & 31;
    // scores[s] = x . M2[b,s,:]  (M2 = kproj @ Wq, precomputed)
    for (int s = warp; s < TSz; s += 8) {
        const float* m2 = &g_M2[((size_t)b*TSz + s)*Hz];
        float a = 0.f;
        for (int h = lane; h < Hz; h += 32) a += xs[h]*m2[h];
#pragma unroll
        for (int off = 16; off > 0; off >>= 1) a += __shfl_xor_sync(0xffffffffu, a, off);
        if (lane == 0)
            sc[s] = (enc_mask[b*TSz + s] > 0) ? a * (1.f/32.f) : -10000.f;
    }
    __syncthreads();

    // softmax over TS=128 (first 128 threads carry data)
    float v = (tid < TSz) ? sc[tid] : -1e30f;
    float m = v;
#pragma unroll
    for (int off = 16; off > 0; off >>= 1) m = fmaxf(m, __shfl_xor_sync(0xffffffffu, m, off));
    if (lane == 0) red[warp] = m;
    __syncthreads();
    if (tid == 0) { float mm = red[0]; for (int i = 1; i < 8; ++i) mm = fmaxf(mm, red[i]); red[0] = mm; }
    __syncthreads();
    const float smax = red[0];
    float e = (tid < TSz) ? expf(v - smax) : 0.f;
    float s2 = e;
#pragma unroll
    for (int off = 16; off > 0; off >>= 1) s2 += __shfl_xor_sync(0xffffffffu, s2, off);
    __syncthreads();
    if (lane == 0) red[warp] = s2;
    __syncthreads();
    if (tid == 0) { float ss = 0.f; for (int i = 0; i < 8; ++i) ss += red[i]; red[0] = ss; }
    __syncthreads();
    const float inv = 1.f/red[0];
    if (tid < TSz) sc[tid] = e * inv;
    __syncthreads();

    // ctx = w @ enc_out  -> stepin[:, 512:1024]
    for (int ei = tid; ei < ENCz; ei += 256) {
        float a = 0.f;
#pragma unroll 4
        for (int s = 0; s < TSz; ++s) a += sc[s]*enc_out[((size_t)b*TSz + s)*ENCz + ei];
        g_stepin[b*Hz + Ez + ei] = a;
    }
    // next-step embedding -> stepin[:, 0:512]
    if (t + 1 < TTz) {
        for (int ei = tid; ei < Ez; ei += 256)
            g_stepin[b*Hz + ei] = g_embA[((size_t)(t+1)*Bz + b)*Ez + ei];
    }
}

// ---------------- launch ----------------
static float* symaddr(const void* sym) {
    void* p = nullptr;
    cudaGetSymbolAddress(&p, sym);
    return (float*)p;
}

extern "C" void kernel_launch(void* const* d_in, const int* in_sizes, int n_in,
                              void* d_out, int out_size)
{
    const int*   tgt       = (const int*)  d_in[0];
    // d_in[1] = tgt_len (unused: reference scans full TT)
    const float* enc_out   = (const float*)d_in[2];
    const int*   enc_mask  = (const int*)  d_in[3];
    const float* embedding = (const float*)d_in[4];
    const float* w_ih      = (const float*)d_in[5];
    const float* w_hh      = (const float*)d_in[6];
    const float* b_ih      = (const float*)d_in[7];
    const float* b_hh      = (const float*)d_in[8];
    const float* Wq        = (const float*)d_in[9];
    const float* Wk        = (const float*)d_in[10];
    const float* proj_w    = (const float*)d_in[11];
    const float* proj_b    = (const float*)d_in[12];
    float* out = (float*)d_out;

    float* p_kproj = symaddr(g_kproj);
    float* p_M2    = symaddr(g_M2);
    float* p_WqT   = symaddr(g_WqT);
    float* p_embA  = symaddr(g_embA);
    float* p_embih = symaddr(g_embih);
    float* p_wpih  = symaddr(g_wpih);
    float* p_pbias = symaddr(g_pbias);
    float* p_xst   = symaddr(g_xstore);

    // prologue
    prep_kernel<<<2048, 256>>>(tgt, embedding, w_ih, w_hh, b_ih, b_hh, Wq);

    // kproj = enc_out @ Wk^T : M=B*TS=4096, N=D=1024, K=ENC=512
    gemm_nt_kernel<64,64,4,4><<<dim3(Dz/64, (Bz*TSz)/64), 256>>>(
        enc_out, ENCz, Wk, ENCz, p_kproj, Dz, ENCz, nullptr);

    // embih = embA @ wpih0[:, :512]^T + pbias0 : M=TT*B=2048, N=4096, K=512
    gemm_nt_kernel<64,64,4,4><<<dim3(G4/64, (TTz*Bz)/64), 256>>>(
        p_embA, Ez, p_wpih, Hz, p_embih, G4, Ez, p_pbias);

    // M2 = kproj @ WqT^T : M=4096, N=H=1024, K=D=1024
    gemm_nt_kernel<64,64,4,4><<<dim3(Hz/64, (Bz*TSz)/64), 256>>>(
        p_kproj, Dz, p_WqT, Dz, p_M2, Hz, Dz, nullptr);

    // sequential decode loop
    for (int t = 0; t < TTz; ++t) {
        for (int l = 0; l < Lz; ++l)
            lstm_layer_kernel<<<G4/64, 128>>>(l, t);
        attn_kernel<<<Bz, 256>>>(t, enc_mask, enc_out);
    }

    // final vocab projection: out[b*TT+t, v] = xstore[b*TT+t] . proj_w[v] + proj_b[v]
    gemm_nt_kernel<128,64,8,8><<<dim3(Vz/64, (Bz*TTz)/128), 128>>>(
        p_xst, Hz, proj_w, Hz, out, Vz, Hz, proj_b);

    (void)in_sizes; (void)n_in; (void)out_size;
}

// round 4
// speedup vs baseline: 1.6322x; 1.6322x over previous
#include <cuda_runtime.h>
#include <math.h>
#include <stdint.h>

// Problem constants (fixed shapes)
#define Bz   32
#define TTz  64
#define TSz  128
#define ENCz 512
#define Ez   512
#define Hz   1024
#define Lz   4
#define Vz   32000
#define Dz   1024
#define G4   4096   // 4*H

// ---------------- scratch (device globals; no allocation allowed) ----------------
__device__ float g_kproj [Bz*TSz*Dz];    // [ (b*TS+s), d ]  enc_out @ Wk^T
__device__ float g_M2    [Bz*TSz*Hz];    // [ (b*TS+s), h ]  kproj @ Wq
__device__ float g_WqT   [Hz*Dz];        // [h, d] = Wq[d, h]
__device__ float g_embA  [TTz*Bz*Ez];    // [ (t*B+b), e ] gathered embeddings
__device__ float g_embih [TTz*Bz*G4];    // [ (t*B+b), r'] emb @ wpih0[:, :512]^T + bias0
__device__ float g_wpih  [Lz*G4*Hz];     // gate-interleaved w_ih  (row r' = 4j+g)
__device__ float g_wphh  [Lz*G4*Hz];     // gate-interleaved w_hh
__device__ float g_pbias [Lz*G4];        // permuted b_ih + b_hh
__device__ float g_h     [Lz*Bz*Hz];
__device__ float g_c     [Lz*Bz*Hz];
__device__ float g_x     [Bz*Hz];        // current layer-stack output (with residual)
__device__ float g_stepin[Bz*Hz];        // [emb_t | ctx]
__device__ float g_xstore[Bz*TTz*Hz];    // [ (b*TT+t), h ] final x per step (proj input)
__device__ float g_gpart [2][Bz*G4];     // split-K partials (seg 0 = ih, seg 1 = hh)

// ---------------- prologue: permute/gather/transpose/init ----------------
__global__ void prep_kernel(const int* __restrict__ tgt,
                            const float* __restrict__ embedding,
                            const float* __restrict__ w_ih,
                            const float* __restrict__ w_hh,
                            const float* __restrict__ b_ih,
                            const float* __restrict__ b_hh,
                            const float* __restrict__ Wq)
{
    const int stride = gridDim.x * blockDim.x;
    const int base   = blockIdx.x * blockDim.x + threadIdx.x;

    // 1) gate-interleave weights: dst row r' = 4j+g <- src row g*1024+j
    for (int i = base; i < Lz*G4*Hz; i += stride) {
        int k  = i & (Hz-1);
        int rp = (i >> 10) & (G4-1);
        int l  = i >> 22;
        int j  = rp >> 2;
        int g  = rp & 3;
        int src = (l*G4 + g*Hz + j)*Hz + k;
        g_wpih[i] = w_ih[src];
        g_wphh[i] = w_hh[src];
    }
    // 2) permuted combined bias
    for (int i = base; i < Lz*G4; i += stride) {
        int rp = i & (G4-1);
        int l  = i >> 12;
        int j  = rp >> 2, g = rp & 3;
        g_pbias[i] = b_ih[l*G4 + g*Hz + j] + b_hh[l*G4 + g*Hz + j];
    }
    // 3) embedding gather: row m = t*B + b
    for (int i = base; i < TTz*Bz*Ez; i += stride) {
        int e = i & (Ez-1);
        int m = i >> 9;
        int t = m / Bz, b = m % Bz;
        int tok = tgt[b*TTz + t];
        g_embA[i] = embedding[(size_t)tok*Ez + e];
    }
    // 4) Wq transpose
    for (int i = base; i < Hz*Dz; i += stride) {
        int d = i & (Dz-1);
        int h = i >> 10;
        g_WqT[i] = Wq[d*Hz + h];
    }
    // 5) zero states
    for (int i = base; i < Lz*Bz*Hz; i += stride) { g_h[i] = 0.f; g_c[i] = 0.f; }
    // 6) stepin for t=0
    for (int i = base; i < Bz*Hz; i += stride) {
        int p = i & (Hz-1);
        int b = i >> 10;
        g_stepin[i] = (p < Ez) ? embedding[(size_t)tgt[b*TTz + 0]*Ez + p] : 0.f;
    }
}

// ---------------- fp32 NT GEMM, 128x128 tile, 8x8 micro, double-buffered ----------
// C[m,n] = sum_k A[m,k]*B[n,k] (+bias[n]).  M%128==0, N%128==0, K%8==0.
__global__ __launch_bounds__(256) void gemm128_kernel(
    const float* __restrict__ A, int lda,
    const float* __restrict__ Bm, int ldb,
    float* __restrict__ C, int ldc,
    int K, const float* __restrict__ bias)
{
    __shared__ float As[2][8][128];
    __shared__ float Bs[2][8][128];
    const int m0 = blockIdx.y * 128, n0 = blockIdx.x * 128;
    const int tid = threadIdx.x;
    const int lm = tid >> 1, lk = (tid & 1) * 4;
    const int tx = tid & 15, ty = tid >> 4;
    const float* Ag = A  + (size_t)(m0 + lm) * lda + lk;
    const float* Bg = Bm + (size_t)(n0 + lm) * ldb + lk;

    float acc[8][8];
#pragma unroll
    for (int i = 0; i < 8; ++i)
#pragma unroll
        for (int j = 0; j < 8; ++j) acc[i][j] = 0.f;

    float4 av = *(const float4*)Ag;
    float4 bv = *(const float4*)Bg;
    As[0][lk+0][lm] = av.x; As[0][lk+1][lm] = av.y; As[0][lk+2][lm] = av.z; As[0][lk+3][lm] = av.w;
    Bs[0][lk+0][lm] = bv.x; Bs[0][lk+1][lm] = bv.y; Bs[0][lk+2][lm] = bv.z; Bs[0][lk+3][lm] = bv.w;
    __syncthreads();

    const int nk = K >> 3;
    for (int kt = 0; kt < nk; ++kt) {
        const int cur = kt & 1;
        if (kt + 1 < nk) {
            av = *(const float4*)(Ag + (size_t)(kt + 1) * 8);
            bv = *(const float4*)(Bg + (size_t)(kt + 1) * 8);
        }
#pragma unroll
        for (int kk = 0; kk < 8; ++kk) {
            float a[8], b[8];
            *(float4*)&a[0] = *(const float4*)&As[cur][kk][ty*8];
            *(float4*)&a[4] = *(const float4*)&As[cur][kk][ty*8+4];
            *(float4*)&b[0] = *(const float4*)&Bs[cur][kk][tx*8];
            *(float4*)&b[4] = *(const float4*)&Bs[cur][kk][tx*8+4];
#pragma unroll
            for (int i = 0; i < 8; ++i)
#pragma unroll
                for (int j = 0; j < 8; ++j) acc[i][j] += a[i]*b[j];
        }
        if (kt + 1 < nk) {
            const int nx = cur ^ 1;
            As[nx][lk+0][lm] = av.x; As[nx][lk+1][lm] = av.y; As[nx][lk+2][lm] = av.z; As[nx][lk+3][lm] = av.w;
            Bs[nx][lk+0][lm] = bv.x; Bs[nx][lk+1][lm] = bv.y; Bs[nx][lk+2][lm] = bv.z; Bs[nx][lk+3][lm] = bv.w;
        }
        __syncthreads();
    }

    float bcol[8];
#pragma unroll
    for (int j = 0; j < 8; ++j) bcol[j] = bias ? bias[n0 + tx*8 + j] : 0.f;
#pragma unroll
    for (int i = 0; i < 8; ++i) {
        const size_t row = (size_t)(m0 + ty*8 + i) * ldc;
        float4 v0 = make_float4(acc[i][0]+bcol[0], acc[i][1]+bcol[1], acc[i][2]+bcol[2], acc[i][3]+bcol[3]);
        float4 v1 = make_float4(acc[i][4]+bcol[4], acc[i][5]+bcol[5], acc[i][6]+bcol[6], acc[i][7]+bcol[7]);
        *(float4*)&C[row + n0 + tx*8]     = v0;
        *(float4*)&C[row + n0 + tx*8 + 4] = v1;
    }
}

// ---------------- LSTM gates GEMM, split-K across 2 segments -------------------
// grid (64, 2): x = 64-wide r' tile, y = segment (0: x@Wih, 1: h@Whh). 256 threads.
// Block tile 32(b) x 64(r'), micro 2x4, double-buffered.
__global__ __launch_bounds__(256) void gates_kernel(int l)
{
    __shared__ float As[2][16][32];
    __shared__ float Ws[2][16][64];
    const int seg = blockIdx.y;
    const int n0  = blockIdx.x * 64;
    const int tid = threadIdx.x;

    const float* Ap; const float* Wp; int K;
    if (seg == 0) {
        if (l == 0) { Ap = g_stepin + Ez; Wp = g_wpih + Ez; K = Ez; }
        else        { Ap = g_x;           Wp = g_wpih + (size_t)l*G4*Hz; K = Hz; }
    } else          { Ap = g_h + (size_t)l*Bz*Hz; Wp = g_wphh + (size_t)l*G4*Hz; K = Hz; }

    const int tx = tid & 15, ty = tid >> 4;
    const int am = tid >> 2, ak = (tid & 3) * 4;      // A loaders: threads < 128
    const int wn = tid >> 2, wk = (tid & 3) * 4;      // W loaders: all 256 threads

    float acc[2][4];
#pragma unroll
    for (int i = 0; i < 2; ++i)
#pragma unroll
        for (int j = 0; j < 4; ++j) acc[i][j] = 0.f;

    float4 av = make_float4(0.f,0.f,0.f,0.f), wv;
    if (tid < 128) av = *(const float4*)&Ap[(size_t)am*Hz + ak];
    wv = *(const float4*)&Wp[(size_t)(n0 + wn)*Hz + wk];
    if (tid < 128) {
        As[0][ak+0][am] = av.x; As[0][ak+1][am] = av.y; As[0][ak+2][am] = av.z; As[0][ak+3][am] = av.w;
    }
    Ws[0][wk+0][wn] = wv.x; Ws[0][wk+1][wn] = wv.y; Ws[0][wk+2][wn] = wv.z; Ws[0][wk+3][wn] = wv.w;
    __syncthreads();

    const int nk = K >> 4;
    for (int kt = 0; kt < nk; ++kt) {
        const int cur = kt & 1;
        if (kt + 1 < nk) {
            const int ko = (kt + 1) * 16;
            if (tid < 128) av = *(const float4*)&Ap[(size_t)am*Hz + ko + ak];
            wv = *(const float4*)&Wp[(size_t)(n0 + wn)*Hz + ko + wk];
        }
#pragma unroll
        for (int kk = 0; kk < 16; ++kk) {
            float2 a = *(const float2*)&As[cur][kk][ty*2];
            float4 w = *(const float4*)&Ws[cur][kk][tx*4];
            acc[0][0] += a.x*w.x; acc[0][1] += a.x*w.y; acc[0][2] += a.x*w.z; acc[0][3] += a.x*w.w;
            acc[1][0] += a.y*w.x; acc[1][1] += a.y*w.y; acc[1][2] += a.y*w.z; acc[1][3] += a.y*w.w;
        }
        if (kt + 1 < nk) {
            const int nx = cur ^ 1;
            if (tid < 128) {
                As[nx][ak+0][am] = av.x; As[nx][ak+1][am] = av.y; As[nx][ak+2][am] = av.z; As[nx][ak+3][am] = av.w;
            }
            Ws[nx][wk+0][wn] = wv.x; Ws[nx][wk+1][wn] = wv.y; Ws[nx][wk+2][wn] = wv.z; Ws[nx][wk+3][wn] = wv.w;
        }
        __syncthreads();
    }

#pragma unroll
    for (int i = 0; i < 2; ++i) {
        const int b = ty*2 + i;
        *(float4*)&g_gpart[seg][b*G4 + n0 + tx*4] =
            make_float4(acc[i][0], acc[i][1], acc[i][2], acc[i][3]);
    }
}

// ---------------- cell epilogue: combine partials + nonlinearity ----------------
__global__ void cell_kernel(int l, int t)
{
    const int idx = blockIdx.x * blockDim.x + threadIdx.x;  // 0..32767 over (b, j)
    const int b = idx >> 10, j = idx & 1023;
    const int rb = j * 4;
    float4 p0 = *(const float4*)&g_gpart[0][b*G4 + rb];
    float4 p1 = *(const float4*)&g_gpart[1][b*G4 + rb];
    float4 bb = (l == 0) ? *(const float4*)&g_embih[((size_t)t*Bz + b)*G4 + rb]
                         : *(const float4*)&g_pbias[l*G4 + rb];
    float iv = p0.x + p1.x + bb.x;
    float fv = p0.y + p1.y + bb.y;
    float gv = p0.z + p1.z + bb.z;
    float ov = p0.w + p1.w + bb.w;
    float ig = 1.f/(1.f + expf(-iv));
    float fg = 1.f/(1.f + expf(-fv));
    float og = 1.f/(1.f + expf(-ov));
    const int ci = (l*Bz + b)*Hz + j;
    float c2 = fg * g_c[ci] + ig * tanhf(gv);
    g_c[ci] = c2;
    float h2 = og * tanhf(c2);
    g_h[ci] = h2;
    float x = h2 + ((l >= 2) ? g_stepin[b*Hz + j] : 0.f);
    g_x[b*Hz + j] = x;
    if (l == 3) g_xstore[((size_t)b*TTz + t)*Hz + j] = x;
}

// ---------------- attention + next-step input (one block per batch) ----------------
__global__ void attn_kernel(int t,
                            const int*   __restrict__ enc_mask,
                            const float* __restrict__ enc_out)
{
    const int b   = blockIdx.x;
    const int tid = threadIdx.x;   // 256
    __shared__ float xs[Hz];
    __shared__ float sc[TSz];
    __shared__ float red[8];

    for (int i = tid; i < Hz; i += 256) xs[i] = g_x[b*Hz + i];
    __syncthreads();

    const int warp = tid >> 5, lane = tid & 31;
    for (int s = warp; s < TSz; s += 8) {
        const float* m2 = &g_M2[((size_t)b*TSz + s)*Hz];
        float a = 0.f;
        for (int h = lane; h < Hz; h += 32) a += xs[h]*m2[h];
#pragma unroll
        for (int off = 16; off > 0; off >>= 1) a += __shfl_xor_sync(0xffffffffu, a, off);
        if (lane == 0)
            sc[s] = (enc_mask[b*TSz + s] > 0) ? a * (1.f/32.f) : -10000.f;
    }
    __syncthreads();

    float v = (tid < TSz) ? sc[tid] : -1e30f;
    float m = v;
#pragma unroll
    for (int off = 16; off > 0; off >>= 1) m = fmaxf(m, __shfl_xor_sync(0xffffffffu, m, off));
    if (lane == 0) red[warp] = m;
    __syncthreads();
    if (tid == 0) { float mm = red[0]; for (int i = 1; i < 8; ++i) mm = fmaxf(mm, red[i]); red[0] = mm; }
    __syncthreads();
    const float smax = red[0];
    float e = (tid < TSz) ? expf(v - smax) : 0.f;
    float s2 = e;
#pragma unroll
    for (int off = 16; off > 0; off >>= 1) s2 += __shfl_xor_sync(0xffffffffu, s2, off);
    __syncthreads();
    if (lane == 0) red[warp] = s2;
    __syncthreads();
    if (tid == 0) { float ss = 0.f; for (int i = 0; i < 8; ++i) ss += red[i]; red[0] = ss; }
    __syncthreads();
    const float inv = 1.f/red[0];
    if (tid < TSz) sc[tid] = e * inv;
    __syncthreads();

    for (int ei = tid; ei < ENCz; ei += 256) {
        float a = 0.f;
#pragma unroll 4
        for (int s = 0; s < TSz; ++s) a += sc[s]*enc_out[((size_t)b*TSz + s)*ENCz + ei];
        g_stepin[b*Hz + Ez + ei] = a;
    }
    if (t + 1 < TTz) {
        for (int ei = tid; ei < Ez; ei += 256)
            g_stepin[b*Hz + ei] = g_embA[((size_t)(t+1)*Bz + b)*Ez + ei];
    }
}

// ---------------- vocab projection via tf32 mma.sync --------------------------
__device__ __forceinline__ uint32_t f2tf(float x) {
    uint32_t r; asm("cvt.rna.tf32.f32 %0, %1;" : "=r"(r) : "f"(x)); return r;
}

// C[2048, 32000] = X[2048,1024] @ W[32000,1024]^T + bias. Block tile 64x128,
// 8 warps (4 m x 2 n), warp tile 16x64, mma m16n8k8 tf32, fp32 accumulate.
__global__ __launch_bounds__(256) void proj_mma_kernel(
    const float* __restrict__ X,
    const float* __restrict__ W,
    const float* __restrict__ bias,
    float* __restrict__ C)
{
    __shared__ uint32_t Xs[64][18];
    __shared__ uint32_t Ws[128][18];
    const int m0 = blockIdx.y * 64, n0 = blockIdx.x * 128;
    const int tid = threadIdx.x, warp = tid >> 5, lane = tid & 31;
    const int wm = warp & 3, wn = warp >> 2;
    const int g = lane >> 2, tig = lane & 3;

    float acc[8][4];
#pragma unroll
    for (int i = 0; i < 8; ++i)
#pragma unroll
        for (int j = 0; j < 4; ++j) acc[i][j] = 0.f;

    const int xm = tid >> 2, xk = (tid & 3) * 4;

    for (int k0 = 0; k0 < Hz; k0 += 16) {
        __syncthreads();
        {
            float4 v = *(const float4*)&X[(size_t)(m0 + xm)*Hz + k0 + xk];
            Xs[xm][xk+0] = f2tf(v.x); Xs[xm][xk+1] = f2tf(v.y);
            Xs[xm][xk+2] = f2tf(v.z); Xs[xm][xk+3] = f2tf(v.w);
        }
#pragma unroll
        for (int it = 0; it < 2; ++it) {
            const int n = xm + it*64;
            float4 v = *(const float4*)&W[(size_t)(n0 + n)*Hz + k0 + xk];
            Ws[n][xk+0] = f2tf(v.x); Ws[n][xk+1] = f2tf(v.y);
            Ws[n][xk+2] = f2tf(v.z); Ws[n][xk+3] = f2tf(v.w);
        }
        __syncthreads();
#pragma unroll
        for (int kh = 0; kh < 16; kh += 8) {
            uint32_t a0 = Xs[wm*16 + g    ][kh + tig];
            uint32_t a1 = Xs[wm*16 + g + 8][kh + tig];
            uint32_t a2 = Xs[wm*16 + g    ][kh + tig + 4];
            uint32_t a3 = Xs[wm*16 + g + 8][kh + tig + 4];
#pragma unroll
            for (int nt = 0; nt < 8; ++nt) {
                const uint32_t* wr = &Ws[wn*64 + nt*8 + g][kh];
                uint32_t b0 = wr[tig], b1 = wr[tig + 4];
                asm volatile(
                    "mma.sync.aligned.m16n8k8.row.col.f32.tf32.tf32.f32 "
                    "{%0,%1,%2,%3}, {%4,%5,%6,%7}, {%8,%9}, {%0,%1,%2,%3};"
                    : "+f"(acc[nt][0]), "+f"(acc[nt][1]), "+f"(acc[nt][2]), "+f"(acc[nt][3])
                    : "r"(a0), "r"(a1), "r"(a2), "r"(a3), "r"(b0), "r"(b1));
            }
        }
    }

#pragma unroll
    for (int nt = 0; nt < 8; ++nt) {
        const int n = n0 + wn*64 + nt*8 + tig*2;
        const float b0v = bias[n], b1v = bias[n+1];
        const size_t r0 = (size_t)(m0 + wm*16 + g) * Vz + n;
        const size_t r1 = r0 + (size_t)8 * Vz;
        float2 v0 = make_float2(acc[nt][0] + b0v, acc[nt][1] + b1v);
        float2 v1 = make_float2(acc[nt][2] + b0v, acc[nt][3] + b1v);
        *(float2*)&C[r0] = v0;
        *(float2*)&C[r1] = v1;
    }
}

// ---------------- launch ----------------
static float* symaddr(const void* sym) {
    void* p = nullptr;
    cudaGetSymbolAddress(&p, sym);
    return (float*)p;
}

extern "C" void kernel_launch(void* const* d_in, const int* in_sizes, int n_in,
                              void* d_out, int out_size)
{
    const int*   tgt       = (const int*)  d_in[0];
    const float* enc_out   = (const float*)d_in[2];
    const int*   enc_mask  = (const int*)  d_in[3];
    const float* embedding = (const float*)d_in[4];
    const float* w_ih      = (const float*)d_in[5];
    const float* w_hh      = (const float*)d_in[6];
    const float* b_ih      = (const float*)d_in[7];
    const float* b_hh      = (const float*)d_in[8];
    const float* Wq        = (const float*)d_in[9];
    const float* Wk        = (const float*)d_in[10];
    const float* proj_w    = (const float*)d_in[11];
    const float* proj_b    = (const float*)d_in[12];
    float* out = (float*)d_out;

    float* p_kproj = symaddr(g_kproj);
    float* p_M2    = symaddr(g_M2);
    float* p_WqT   = symaddr(g_WqT);
    float* p_embA  = symaddr(g_embA);
    float* p_embih = symaddr(g_embih);
    float* p_wpih  = symaddr(g_wpih);
    float* p_pbias = symaddr(g_pbias);
    float* p_xst   = symaddr(g_xstore);

    prep_kernel<<<2048, 256>>>(tgt, embedding, w_ih, w_hh, b_ih, b_hh, Wq);

    // kproj = enc_out @ Wk^T : M=4096, N=1024, K=512
    gemm128_kernel<<<dim3(Dz/128, (Bz*TSz)/128), 256>>>(
        enc_out, ENCz, Wk, ENCz, p_kproj, Dz, ENCz, nullptr);

    // embih = embA @ wpih0[:, :512]^T + pbias0 : M=2048, N=4096, K=512
    gemm128_kernel<<<dim3(G4/128, (TTz*Bz)/128), 256>>>(
        p_embA, Ez, p_wpih, Hz, p_embih, G4, Ez, p_pbias);

    // M2 = kproj @ WqT^T : M=4096, N=1024, K=1024
    gemm128_kernel<<<dim3(Hz/128, (Bz*TSz)/128), 256>>>(
        p_kproj, Dz, p_WqT, Dz, p_M2, Hz, Dz, nullptr);

    for (int t = 0; t < TTz; ++t) {
        for (int l = 0; l < Lz; ++l) {
            gates_kernel<<<dim3(64, 2), 256>>>(l);
            cell_kernel<<<128, 256>>>(l, t);
        }
        attn_kernel<<<Bz, 256>>>(t, enc_mask, enc_out);
    }

    // vocab projection (tf32 mma): out = xstore @ proj_w^T + proj_b
    proj_mma_kernel<<<dim3(Vz/128, (Bz*TTz)/64), 256>>>(p_xst, proj_w, proj_b, out);

    (void)in_sizes; (void)n_in; (void)out_size;
}

// round 7
// speedup vs baseline: 1.8278x; 1.1198x over previous
#include <cuda_runtime.h>
#include <math.h>
#include <stdint.h>

// Problem constants (fixed shapes)
#define Bz   32
#define TTz  64
#define TSz  128
#define ENCz 512
#define Ez   512
#define Hz   1024
#define Lz   4
#define Vz   32000
#define Dz   1024
#define G4   4096   // 4*H

// ---------------- scratch (device globals; no allocation allowed) ----------------
__device__ float g_kproj [Bz*TSz*Dz];    // [ (b*TS+s), d ]  enc_out @ Wk^T
__device__ float g_M2    [Bz*TSz*Hz];    // [ (b*TS+s), h ]  kproj @ Wq
__device__ float g_WqT   [Hz*Dz];        // [h, d] = Wq[d, h]
__device__ float g_embA  [TTz*Bz*Ez];    // [ (t*B+b), e ] gathered embeddings
__device__ float g_embih [TTz*Bz*G4];    // [ (t*B+b), r'] emb @ wpih0[:, :512]^T + bias0
__device__ float g_wpih  [Lz*G4*Hz];     // gate-interleaved w_ih, tf32-rounded
__device__ float g_wphh  [Lz*G4*Hz];     // gate-interleaved w_hh, tf32-rounded
__device__ float g_pbias [Lz*G4];        // permuted b_ih + b_hh
__device__ float g_hb    [2][Lz*Bz*Hz];  // h state, ping-pong on t parity (race fix)
__device__ float g_c     [Lz*Bz*Hz];     // c state (read only at own index -> safe)
__device__ float g_xb    [2][Bz*Hz];     // layer output, ping-pong on layer parity
__device__ float g_stepin[Bz*Hz];        // [emb_t | ctx]
__device__ float g_xstore[Bz*TTz*Hz];    // [ (b*TT+t), h ] final x per step (proj input)

__device__ __forceinline__ uint32_t f2tf(float x) {
    uint32_t r; asm("cvt.rna.tf32.f32 %0, %1;" : "=r"(r) : "f"(x)); return r;
}

// ---------------- prologue: permute/gather/transpose/init ----------------
__global__ void prep_kernel(const int* __restrict__ tgt,
                            const float* __restrict__ embedding,
                            const float* __restrict__ w_ih,
                            const float* __restrict__ w_hh,
                            const float* __restrict__ b_ih,
                            const float* __restrict__ b_hh,
                            const float* __restrict__ Wq)
{
    const int stride = gridDim.x * blockDim.x;
    const int base   = blockIdx.x * blockDim.x + threadIdx.x;

    // 1) gate-interleave weights (r' = 4j+g) + tf32 pre-rounding
    for (int i = base; i < Lz*G4*Hz; i += stride) {
        int k  = i & (Hz-1);
        int rp = (i >> 10) & (G4-1);
        int l  = i >> 22;
        int j  = rp >> 2;
        int g  = rp & 3;
        int src = (l*G4 + g*Hz + j)*Hz + k;
        g_wpih[i] = __uint_as_float(f2tf(w_ih[src]));
        g_wphh[i] = __uint_as_float(f2tf(w_hh[src]));
    }
    // 2) permuted combined bias
    for (int i = base; i < Lz*G4; i += stride) {
        int rp = i & (G4-1);
        int l  = i >> 12;
        int j  = rp >> 2, g = rp & 3;
        g_pbias[i] = b_ih[l*G4 + g*Hz + j] + b_hh[l*G4 + g*Hz + j];
    }
    // 3) embedding gather: row m = t*B + b
    for (int i = base; i < TTz*Bz*Ez; i += stride) {
        int e = i & (Ez-1);
        int m = i >> 9;
        int t = m / Bz, b = m % Bz;
        int tok = tgt[b*TTz + t];
        g_embA[i] = embedding[(size_t)tok*Ez + e];
    }
    // 4) Wq transpose
    for (int i = base; i < Hz*Dz; i += stride) {
        int d = i & (Dz-1);
        int h = i >> 10;
        g_WqT[i] = Wq[d*Hz + h];
    }
    // 5) zero states (both h buffers + c)
    for (int i = base; i < 2*Lz*Bz*Hz; i += stride) ((float*)g_hb)[i] = 0.f;
    for (int i = base; i < Lz*Bz*Hz;   i += stride) g_c[i] = 0.f;
    // 6) stepin for t=0
    for (int i = base; i < Bz*Hz; i += stride) {
        int p = i & (Hz-1);
        int b = i >> 10;
        g_stepin[i] = (p < Ez) ? embedding[(size_t)tgt[b*TTz + 0]*Ez + p] : 0.f;
    }
}

// ---------------- fp32 NT GEMM, 128x128 tile, 8x8 micro, double-buffered ----------
__global__ __launch_bounds__(256) void gemm128_kernel(
    const float* __restrict__ A, int lda,
    const float* __restrict__ Bm, int ldb,
    float* __restrict__ C, int ldc,
    int K, const float* __restrict__ bias)
{
    __shared__ float As[2][8][128];
    __shared__ float Bs[2][8][128];
    const int m0 = blockIdx.y * 128, n0 = blockIdx.x * 128;
    const int tid = threadIdx.x;
    const int lm = tid >> 1, lk = (tid & 1) * 4;
    const int tx = tid & 15, ty = tid >> 4;
    const float* Ag = A  + (size_t)(m0 + lm) * lda + lk;
    const float* Bg = Bm + (size_t)(n0 + lm) * ldb + lk;

    float acc[8][8];
#pragma unroll
    for (int i = 0; i < 8; ++i)
#pragma unroll
        for (int j = 0; j < 8; ++j) acc[i][j] = 0.f;

    float4 av = *(const float4*)Ag;
    float4 bv = *(const float4*)Bg;
    As[0][lk+0][lm] = av.x; As[0][lk+1][lm] = av.y; As[0][lk+2][lm] = av.z; As[0][lk+3][lm] = av.w;
    Bs[0][lk+0][lm] = bv.x; Bs[0][lk+1][lm] = bv.y; Bs[0][lk+2][lm] = bv.z; Bs[0][lk+3][lm] = bv.w;
    __syncthreads();

    const int nk = K >> 3;
    for (int kt = 0; kt < nk; ++kt) {
        const int cur = kt & 1;
        if (kt + 1 < nk) {
            av = *(const float4*)(Ag + (size_t)(kt + 1) * 8);
            bv = *(const float4*)(Bg + (size_t)(kt + 1) * 8);
        }
#pragma unroll
        for (int kk = 0; kk < 8; ++kk) {
            float a[8], b[8];
            *(float4*)&a[0] = *(const float4*)&As[cur][kk][ty*8];
            *(float4*)&a[4] = *(const float4*)&As[cur][kk][ty*8+4];
            *(float4*)&b[0] = *(const float4*)&Bs[cur][kk][tx*8];
            *(float4*)&b[4] = *(const float4*)&Bs[cur][kk][tx*8+4];
#pragma unroll
            for (int i = 0; i < 8; ++i)
#pragma unroll
                for (int j = 0; j < 8; ++j) acc[i][j] += a[i]*b[j];
        }
        if (kt + 1 < nk) {
            const int nx = cur ^ 1;
            As[nx][lk+0][lm] = av.x; As[nx][lk+1][lm] = av.y; As[nx][lk+2][lm] = av.z; As[nx][lk+3][lm] = av.w;
            Bs[nx][lk+0][lm] = bv.x; Bs[nx][lk+1][lm] = bv.y; Bs[nx][lk+2][lm] = bv.z; Bs[nx][lk+3][lm] = bv.w;
        }
        __syncthreads();
    }

    float bcol[8];
#pragma unroll
    for (int j = 0; j < 8; ++j) bcol[j] = bias ? bias[n0 + tx*8 + j] : 0.f;
#pragma unroll
    for (int i = 0; i < 8; ++i) {
        const size_t row = (size_t)(m0 + ty*8 + i) * ldc;
        float4 v0 = make_float4(acc[i][0]+bcol[0], acc[i][1]+bcol[1], acc[i][2]+bcol[2], acc[i][3]+bcol[3]);
        float4 v1 = make_float4(acc[i][4]+bcol[4], acc[i][5]+bcol[5], acc[i][6]+bcol[6], acc[i][7]+bcol[7]);
        *(float4*)&C[row + n0 + tx*8]     = v0;
        *(float4*)&C[row + n0 + tx*8 + 4] = v1;
    }
}

// ---------------- fused LSTM layer: tf32 mma gates GEMM + cell epilogue --------
// grid = 64 blocks, 256 threads (8 warps: 2 m x 4 n). Block tile 32(b) x 64(r').
// K streams two segments (x@Wih, h@Whh). Weights pre-rounded to tf32 in prep.
// RACE-SAFE: reads x from g_xb[l&1] (l>=1) / g_stepin (l=0), writes g_xb[(l+1)&1];
// reads h from g_hb[t&1], writes g_hb[(t+1)&1]. g_c is index-local (safe).
__global__ __launch_bounds__(256) void gates_mma_kernel(int l, int t)
{
    __shared__ uint32_t As[2][32][36];
    __shared__ uint32_t Ws[2][64][36];
    __shared__ float    gsm[32][68];

    const int tid  = threadIdx.x;
    const int warp = tid >> 5, lane = tid & 31;
    const int wm   = warp & 1, wn = warp >> 1;     // 2 m-warps x 4 n-warps
    const int g    = lane >> 2, tig = lane & 3;
    const int n0   = blockIdx.x * 64;

    const float* hp_r = g_hb[t & 1] + (size_t)l*Bz*Hz;       // read h
    float*       hp_w = g_hb[(t + 1) & 1] + (size_t)l*Bz*Hz; // write h
    const float* xp_r = g_xb[l & 1];                          // read x (l>=1)
    float*       xp_w = g_xb[(l + 1) & 1];                    // write x

    // loaders (chunk = 32 k)
    const int ar = tid >> 3, ak = (tid & 7) * 4;   // A: 32 rows x 32 k
    const int wr = tid >> 3, wk = (tid & 7) * 4;   // W: rows wr, wr+32

    float acc[2][4];
#pragma unroll
    for (int i = 0; i < 2; ++i)
#pragma unroll
        for (int j = 0; j < 4; ++j) acc[i][j] = 0.f;

    for (int seg = 0; seg < 2; ++seg) {
        const float* Ap; const float* Wp; int K;
        if (seg == 0) {
            if (l == 0) { Ap = g_stepin + Ez; Wp = g_wpih + Ez; K = Ez; }
            else        { Ap = xp_r;          Wp = g_wpih + (size_t)l*G4*Hz; K = Hz; }
        } else          { Ap = hp_r;          Wp = g_wphh + (size_t)l*G4*Hz; K = Hz; }

        const int nchunk = K >> 5;

        float4 av = *(const float4*)&Ap[(size_t)ar*Hz + ak];
        uint4  w0 = *(const uint4*)&Wp[(size_t)(n0 + wr)*Hz + wk];
        uint4  w1 = *(const uint4*)&Wp[(size_t)(n0 + wr + 32)*Hz + wk];
        As[0][ar][ak+0] = f2tf(av.x); As[0][ar][ak+1] = f2tf(av.y);
        As[0][ar][ak+2] = f2tf(av.z); As[0][ar][ak+3] = f2tf(av.w);
        *(uint4*)&Ws[0][wr][wk]      = w0;
        *(uint4*)&Ws[0][wr+32][wk]   = w1;
        __syncthreads();

        for (int kt = 0; kt < nchunk; ++kt) {
            const int cur = kt & 1;
            if (kt + 1 < nchunk) {
                const int ko = (kt + 1) * 32;
                av = *(const float4*)&Ap[(size_t)ar*Hz + ko + ak];
                w0 = *(const uint4*)&Wp[(size_t)(n0 + wr)*Hz + ko + wk];
                w1 = *(const uint4*)&Wp[(size_t)(n0 + wr + 32)*Hz + ko + wk];
            }
#pragma unroll
            for (int kh = 0; kh < 32; kh += 8) {
                uint32_t a0 = As[cur][wm*16 + g    ][kh + tig];
                uint32_t a1 = As[cur][wm*16 + g + 8][kh + tig];
                uint32_t a2 = As[cur][wm*16 + g    ][kh + tig + 4];
                uint32_t a3 = As[cur][wm*16 + g + 8][kh + tig + 4];
#pragma unroll
                for (int nt = 0; nt < 2; ++nt) {
                    const uint32_t* brow = &Ws[cur][wn*16 + nt*8 + g][kh];
                    uint32_t b0 = brow[tig], b1 = brow[tig + 4];
                    asm volatile(
                        "mma.sync.aligned.m16n8k8.row.col.f32.tf32.tf32.f32 "
                        "{%0,%1,%2,%3}, {%4,%5,%6,%7}, {%8,%9}, {%0,%1,%2,%3};"
                        : "+f"(acc[nt][0]), "+f"(acc[nt][1]), "+f"(acc[nt][2]), "+f"(acc[nt][3])
                        : "r"(a0), "r"(a1), "r"(a2), "r"(a3), "r"(b0), "r"(b1));
                }
            }
            if (kt + 1 < nchunk) {
                const int nx = cur ^ 1;
                As[nx][ar][ak+0] = f2tf(av.x); As[nx][ar][ak+1] = f2tf(av.y);
                As[nx][ar][ak+2] = f2tf(av.z); As[nx][ar][ak+3] = f2tf(av.w);
                *(uint4*)&Ws[nx][wr][wk]    = w0;
                *(uint4*)&Ws[nx][wr+32][wk] = w1;
            }
            __syncthreads();
        }
    }

    // stage accumulators to smem: rows = b, cols = r' within tile
#pragma unroll
    for (int nt = 0; nt < 2; ++nt) {
        const int c = wn*16 + nt*8 + tig*2;
        const int r0 = wm*16 + g;
        gsm[r0    ][c]   = acc[nt][0];
        gsm[r0    ][c+1] = acc[nt][1];
        gsm[r0 + 8][c]   = acc[nt][2];
        gsm[r0 + 8][c+1] = acc[nt][3];
    }
    __syncthreads();

    // cell epilogue: 512 units (32 b x 16 j_local), 2 per thread
#pragma unroll
    for (int rep = 0; rep < 2; ++rep) {
        const int u  = tid + rep*256;
        const int b  = u >> 4;
        const int jl = u & 15;
        const int rl = jl * 4;
        float iv = gsm[b][rl+0];
        float fv = gsm[b][rl+1];
        float gv = gsm[b][rl+2];
        float ov = gsm[b][rl+3];
        if (l == 0) {
            float4 e = *(const float4*)&g_embih[((size_t)t*Bz + b)*G4 + n0 + rl];
            iv += e.x; fv += e.y; gv += e.z; ov += e.w;
        } else {
            float4 pb = *(const float4*)&g_pbias[l*G4 + n0 + rl];
            iv += pb.x; fv += pb.y; gv += pb.z; ov += pb.w;
        }
        float ig = 1.f/(1.f + expf(-iv));
        float fg = 1.f/(1.f + expf(-fv));
        float og = 1.f/(1.f + expf(-ov));
        const int j  = blockIdx.x*16 + jl;
        const int ci = (l*Bz + b)*Hz + j;
        float c2 = fg * g_c[ci] + ig * tanhf(gv);
        g_c[ci] = c2;
        float h2 = og * tanhf(c2);
        hp_w[b*Hz + j] = h2;
        float x = h2 + ((l >= 2) ? g_stepin[b*Hz + j] : 0.f);
        xp_w[b*Hz + j] = x;
        if (l == 3) g_xstore[((size_t)b*TTz + t)*Hz + j] = x;
    }
}

// ---------------- attention + next-step input (one block per batch) ----------------
// Reads layer-3 output from g_xb[0] (layer 3 writes buffer (3+1)&1 = 0).
__global__ void attn_kernel(int t,
                            const int*   __restrict__ enc_mask,
                            const float* __restrict__ enc_out)
{
    const int b   = blockIdx.x;
    const int tid = threadIdx.x;   // 256
    __shared__ float xs[Hz];
    __shared__ float sc[TSz];
    __shared__ float red[8];

    for (int i = tid; i < Hz; i += 256) xs[i] = g_xb[0][b*Hz + i];
    __syncthreads();

    const int warp = tid >> 5, lane = tid & 31;
    for (int s = warp; s < TSz; s += 8) {
        const float* m2 = &g_M2[((size_t)b*TSz + s)*Hz];
        float a = 0.f;
        for (int h = lane; h < Hz; h += 32) a += xs[h]*m2[h];
#pragma unroll
        for (int off = 16; off > 0; off >>= 1) a += __shfl_xor_sync(0xffffffffu, a, off);
        if (lane == 0)
            sc[s] = (enc_mask[b*TSz + s] > 0) ? a * (1.f/32.f) : -10000.f;
    }
    __syncthreads();

    float v = (tid < TSz) ? sc[tid] : -1e30f;
    float m = v;
#pragma unroll
    for (int off = 16; off > 0; off >>= 1) m = fmaxf(m, __shfl_xor_sync(0xffffffffu, m, off));
    if (lane == 0) red[warp] = m;
    __syncthreads();
    if (tid == 0) { float mm = red[0]; for (int i = 1; i < 8; ++i) mm = fmaxf(mm, red[i]); red[0] = mm; }
    __syncthreads();
    const float smax = red[0];
    float e = (tid < TSz) ? expf(v - smax) : 0.f;
    float s2 = e;
#pragma unroll
    for (int off = 16; off > 0; off >>= 1) s2 += __shfl_xor_sync(0xffffffffu, s2, off);
    __syncthreads();
    if (lane == 0) red[warp] = s2;
    __syncthreads();
    if (tid == 0) { float ss = 0.f; for (int i = 0; i < 8; ++i) ss += red[i]; red[0] = ss; }
    __syncthreads();
    const float inv = 1.f/red[0];
    if (tid < TSz) sc[tid] = e * inv;
    __syncthreads();

    for (int ei = tid; ei < ENCz; ei += 256) {
        float a = 0.f;
#pragma unroll 4
        for (int s = 0; s < TSz; ++s) a += sc[s]*enc_out[((size_t)b*TSz + s)*ENCz + ei];
        g_stepin[b*Hz + Ez + ei] = a;
    }
    if (t + 1 < TTz) {
        for (int ei = tid; ei < Ez; ei += 256)
            g_stepin[b*Hz + ei] = g_embA[((size_t)(t+1)*Bz + b)*Ez + ei];
    }
}

// ---------------- vocab projection via tf32 mma.sync --------------------------
// C[2048, 32000] = X[2048,1024] @ W[32000,1024]^T + bias. Block tile 64x128,
// 8 warps (4 m x 2 n), warp tile 16x64, mma m16n8k8 tf32, fp32 accumulate.
__global__ __launch_bounds__(256) void proj_mma_kernel(
    const float* __restrict__ X,
    const float* __restrict__ W,
    const float* __restrict__ bias,
    float* __restrict__ C)
{
    __shared__ uint32_t Xs[64][18];
    __shared__ uint32_t Ws[128][18];
    const int m0 = blockIdx.y * 64, n0 = blockIdx.x * 128;
    const int tid = threadIdx.x, warp = tid >> 5, lane = tid & 31;
    const int wm = warp & 3, wn = warp >> 2;
    const int g = lane >> 2, tig = lane & 3;

    float acc[8][4];
#pragma unroll
    for (int i = 0; i < 8; ++i)
#pragma unroll
        for (int j = 0; j < 4; ++j) acc[i][j] = 0.f;

    const int xm = tid >> 2, xk = (tid & 3) * 4;

    for (int k0 = 0; k0 < Hz; k0 += 16) {
        __syncthreads();
        {
            float4 v = *(const float4*)&X[(size_t)(m0 + xm)*Hz + k0 + xk];
            Xs[xm][xk+0] = f2tf(v.x); Xs[xm][xk+1] = f2tf(v.y);
            Xs[xm][xk+2] = f2tf(v.z); Xs[xm][xk+3] = f2tf(v.w);
        }
#pragma unroll
        for (int it = 0; it < 2; ++it) {
            const int n = xm + it*64;
            float4 v = *(const float4*)&W[(size_t)(n0 + n)*Hz + k0 + xk];
            Ws[n][xk+0] = f2tf(v.x); Ws[n][xk+1] = f2tf(v.y);
            Ws[n][xk+2] = f2tf(v.z); Ws[n][xk+3] = f2tf(v.w);
        }
        __syncthreads();
#pragma unroll
        for (int kh = 0; kh < 16; kh += 8) {
            uint32_t a0 = Xs[wm*16 + g    ][kh + tig];
            uint32_t a1 = Xs[wm*16 + g + 8][kh + tig];
            uint32_t a2 = Xs[wm*16 + g    ][kh + tig + 4];
            uint32_t a3 = Xs[wm*16 + g + 8][kh + tig + 4];
#pragma unroll
            for (int nt = 0; nt < 8; ++nt) {
                const uint32_t* wr = &Ws[wn*64 + nt*8 + g][kh];
                uint32_t b0 = wr[tig], b1 = wr[tig + 4];
                asm volatile(
                    "mma.sync.aligned.m16n8k8.row.col.f32.tf32.tf32.f32 "
                    "{%0,%1,%2,%3}, {%4,%5,%6,%7}, {%8,%9}, {%0,%1,%2,%3};"
                    : "+f"(acc[nt][0]), "+f"(acc[nt][1]), "+f"(acc[nt][2]), "+f"(acc[nt][3])
                    : "r"(a0), "r"(a1), "r"(a2), "r"(a3), "r"(b0), "r"(b1));
            }
        }
    }

#pragma unroll
    for (int nt = 0; nt < 8; ++nt) {
        const int n = n0 + wn*64 + nt*8 + tig*2;
        const float b0v = bias[n], b1v = bias[n+1];
        const size_t r0 = (size_t)(m0 + wm*16 + g) * Vz + n;
        const size_t r1 = r0 + (size_t)8 * Vz;
        float2 v0 = make_float2(acc[nt][0] + b0v, acc[nt][1] + b1v);
        float2 v1 = make_float2(acc[nt][2] + b0v, acc[nt][3] + b1v);
        *(float2*)&C[r0] = v0;
        *(float2*)&C[r1] = v1;
    }
}

// ---------------- launch ----------------
static float* symaddr(const void* sym) {
    void* p = nullptr;
    cudaGetSymbolAddress(&p, sym);
    return (float*)p;
}

extern "C" void kernel_launch(void* const* d_in, const int* in_sizes, int n_in,
                              void* d_out, int out_size)
{
    const int*   tgt       = (const int*)  d_in[0];
    const float* enc_out   = (const float*)d_in[2];
    const int*   enc_mask  = (const int*)  d_in[3];
    const float* embedding = (const float*)d_in[4];
    const float* w_ih      = (const float*)d_in[5];
    const float* w_hh      = (const float*)d_in[6];
    const float* b_ih      = (const float*)d_in[7];
    const float* b_hh      = (const float*)d_in[8];
    const float* Wq        = (const float*)d_in[9];
    const float* Wk        = (const float*)d_in[10];
    const float* proj_w    = (const float*)d_in[11];
    const float* proj_b    = (const float*)d_in[12];
    float* out = (float*)d_out;

    float* p_kproj = symaddr(g_kproj);
    float* p_M2    = symaddr(g_M2);
    float* p_WqT   = symaddr(g_WqT);
    float* p_embA  = symaddr(g_embA);
    float* p_embih = symaddr(g_embih);
    float* p_wpih  = symaddr(g_wpih);
    float* p_pbias = symaddr(g_pbias);
    float* p_xst   = symaddr(g_xstore);

    prep_kernel<<<2048, 256>>>(tgt, embedding, w_ih, w_hh, b_ih, b_hh, Wq);

    // kproj = enc_out @ Wk^T : M=4096, N=1024, K=512
    gemm128_kernel<<<dim3(Dz/128, (Bz*TSz)/128), 256>>>(
        enc_out, ENCz, Wk, ENCz, p_kproj, Dz, ENCz, nullptr);

    // embih = embA @ wpih0[:, :512]^T + pbias0 : M=2048, N=4096, K=512
    gemm128_kernel<<<dim3(G4/128, (TTz*Bz)/128), 256>>>(
        p_embA, Ez, p_wpih, Hz, p_embih, G4, Ez, p_pbias);

    // M2 = kproj @ WqT^T : M=4096, N=1024, K=1024
    gemm128_kernel<<<dim3(Hz/128, (Bz*TSz)/128), 256>>>(
        p_kproj, Dz, p_WqT, Dz, p_M2, Hz, Dz, nullptr);

    for (int t = 0; t < TTz; ++t) {
        for (int l = 0; l < Lz; ++l)
            gates_mma_kernel<<<64, 256>>>(l, t);
        if (t + 1 < TTz)
            attn_kernel<<<Bz, 256>>>(t, enc_mask, enc_out);
    }

    // vocab projection (tf32 mma): out = xstore @ proj_w^T + proj_b
    proj_mma_kernel<<<dim3(Vz/128, (Bz*TTz)/64), 256>>>(p_xst, proj_w, proj_b, out);

    (void)in_sizes; (void)n_in; (void)out_size;
}

// round 8
// speedup vs baseline: 3.3886x; 1.8539x over previous
#include <cuda_runtime.h>
#include <math.h>
#include <stdint.h>

// Problem constants (fixed shapes)
#define Bz   32
#define TTz  64
#define TSz  128
#define ENCz 512
#define Ez   512
#define Hz   1024
#define Lz   4
#define Vz   32000
#define Dz   1024
#define G4   4096   // 4*H
#define KC   32     // gates k-chunk

// ---------------- scratch (device globals; no allocation allowed) ----------------
__device__ float g_kproj [Bz*TSz*Dz];    // [ (b*TS+s), d ]  enc_out @ Wk^T
__device__ float g_M2    [Bz*TSz*Hz];    // [ (b*TS+s), h ]  kproj @ Wq
__device__ float g_WqT   [Hz*Dz];        // [h, d] = Wq[d, h]
__device__ float g_embA  [TTz*Bz*Ez];    // [ (t*B+b), e ] gathered embeddings
__device__ float g_embih [TTz*Bz*G4];    // [ (t*B+b), r'] emb @ wpih0[:, :512]^T + bias0
__device__ float g_wpih  [Lz*G4*Hz];     // gate-interleaved w_ih, tf32-rounded
__device__ float g_wphh  [Lz*G4*Hz];     // gate-interleaved w_hh, tf32-rounded
__device__ float g_pbias [Lz*G4];        // permuted b_ih + b_hh
__device__ float g_hb    [2][Lz*Bz*Hz];  // h state, ping-pong on t parity
__device__ float g_c     [Lz*Bz*Hz];     // c state (index-local -> race-safe)
__device__ float g_xb    [2][Bz*Hz];     // layer output, ping-pong on layer parity
__device__ float g_stepin[Bz*Hz];        // [emb_t | ctx]
__device__ float g_xstore[Bz*TTz*Hz];    // [ (b*TT+t), h ] final x per step
__device__ float g_scores[Bz*TSz];       // attention scores (masked, scaled)

__device__ __forceinline__ uint32_t f2tf(float x) {
    uint32_t r; asm("cvt.rna.tf32.f32 %0, %1;" : "=r"(r) : "f"(x)); return r;
}
__device__ __forceinline__ void cpa16(uint32_t saddr, const float* g) {
    asm volatile("cp.async.cg.shared.global [%0], [%1], 16;" :: "r"(saddr), "l"(g));
}

// ---------------- prologue: permute/gather/transpose/init ----------------
__global__ void prep_kernel(const int* __restrict__ tgt,
                            const float* __restrict__ embedding,
                            const float* __restrict__ w_ih,
                            const float* __restrict__ w_hh,
                            const float* __restrict__ b_ih,
                            const float* __restrict__ b_hh,
                            const float* __restrict__ Wq)
{
    const int stride = gridDim.x * blockDim.x;
    const int base   = blockIdx.x * blockDim.x + threadIdx.x;

    for (int i = base; i < Lz*G4*Hz; i += stride) {
        int k  = i & (Hz-1);
        int rp = (i >> 10) & (G4-1);
        int l  = i >> 22;
        int j  = rp >> 2;
        int g  = rp & 3;
        int src = (l*G4 + g*Hz + j)*Hz + k;
        g_wpih[i] = __uint_as_float(f2tf(w_ih[src]));
        g_wphh[i] = __uint_as_float(f2tf(w_hh[src]));
    }
    for (int i = base; i < Lz*G4; i += stride) {
        int rp = i & (G4-1);
        int l  = i >> 12;
        int j  = rp >> 2, g = rp & 3;
        g_pbias[i] = b_ih[l*G4 + g*Hz + j] + b_hh[l*G4 + g*Hz + j];
    }
    for (int i = base; i < TTz*Bz*Ez; i += stride) {
        int e = i & (Ez-1);
        int m = i >> 9;
        int t = m / Bz, b = m % Bz;
        int tok = tgt[b*TTz + t];
        g_embA[i] = embedding[(size_t)tok*Ez + e];
    }
    for (int i = base; i < Hz*Dz; i += stride) {
        int d = i & (Dz-1);
        int h = i >> 10;
        g_WqT[i] = Wq[d*Hz + h];
    }
    for (int i = base; i < 2*Lz*Bz*Hz; i += stride) ((float*)g_hb)[i] = 0.f;
    for (int i = base; i < Lz*Bz*Hz;   i += stride) g_c[i] = 0.f;
    for (int i = base; i < Bz*Hz; i += stride) {
        int p = i & (Hz-1);
        int b = i >> 10;
        g_stepin[i] = (p < Ez) ? embedding[(size_t)tgt[b*TTz + 0]*Ez + p] : 0.f;
    }
}

// ---------------- generic tf32 mma NT GEMM (+bias) -----------------------------
// C[M,N] = A[M,lda] @ B[N,ldb]^T. Block 64m x 128n, 8 warps (4m x 2n),
// warp tile 16x64, mma m16n8k8, fp32 accum. M%64==0, N%128==0, K%16==0.
__global__ __launch_bounds__(256) void gemm_tf32_kernel(
    const float* __restrict__ A, int lda,
    const float* __restrict__ W, int ldb,
    float* __restrict__ C, int ldc,
    int K, const float* __restrict__ bias)
{
    __shared__ uint32_t Xs[64][18];
    __shared__ uint32_t Ws[128][18];
    const int m0 = blockIdx.y * 64, n0 = blockIdx.x * 128;
    const int tid = threadIdx.x, warp = tid >> 5, lane = tid & 31;
    const int wm = warp & 3, wn = warp >> 2;
    const int g = lane >> 2, tig = lane & 3;

    float acc[8][4];
#pragma unroll
    for (int i = 0; i < 8; ++i)
#pragma unroll
        for (int j = 0; j < 4; ++j) acc[i][j] = 0.f;

    const int xm = tid >> 2, xk = (tid & 3) * 4;

    for (int k0 = 0; k0 < K; k0 += 16) {
        __syncthreads();
        {
            float4 v = *(const float4*)&A[(size_t)(m0 + xm)*lda + k0 + xk];
            Xs[xm][xk+0] = f2tf(v.x); Xs[xm][xk+1] = f2tf(v.y);
            Xs[xm][xk+2] = f2tf(v.z); Xs[xm][xk+3] = f2tf(v.w);
        }
#pragma unroll
        for (int it = 0; it < 2; ++it) {
            const int n = xm + it*64;
            float4 v = *(const float4*)&W[(size_t)(n0 + n)*ldb + k0 + xk];
            Ws[n][xk+0] = f2tf(v.x); Ws[n][xk+1] = f2tf(v.y);
            Ws[n][xk+2] = f2tf(v.z); Ws[n][xk+3] = f2tf(v.w);
        }
        __syncthreads();
#pragma unroll
        for (int kh = 0; kh < 16; kh += 8) {
            uint32_t a0 = Xs[wm*16 + g    ][kh + tig];
            uint32_t a1 = Xs[wm*16 + g + 8][kh + tig];
            uint32_t a2 = Xs[wm*16 + g    ][kh + tig + 4];
            uint32_t a3 = Xs[wm*16 + g + 8][kh + tig + 4];
#pragma unroll
            for (int nt = 0; nt < 8; ++nt) {
                const uint32_t* wr = &Ws[wn*64 + nt*8 + g][kh];
                uint32_t b0 = wr[tig], b1 = wr[tig + 4];
                asm volatile(
                    "mma.sync.aligned.m16n8k8.row.col.f32.tf32.tf32.f32 "
                    "{%0,%1,%2,%3}, {%4,%5,%6,%7}, {%8,%9}, {%0,%1,%2,%3};"
                    : "+f"(acc[nt][0]), "+f"(acc[nt][1]), "+f"(acc[nt][2]), "+f"(acc[nt][3])
                    : "r"(a0), "r"(a1), "r"(a2), "r"(a3), "r"(b0), "r"(b1));
            }
        }
    }

#pragma unroll
    for (int nt = 0; nt < 8; ++nt) {
        const int n = n0 + wn*64 + nt*8 + tig*2;
        const float b0v = bias ? bias[n]   : 0.f;
        const float b1v = bias ? bias[n+1] : 0.f;
        const size_t r0 = (size_t)(m0 + wm*16 + g) * ldc + n;
        const size_t r1 = r0 + (size_t)8 * ldc;
        float2 v0 = make_float2(acc[nt][0] + b0v, acc[nt][1] + b1v);
        float2 v1 = make_float2(acc[nt][2] + b0v, acc[nt][3] + b1v);
        *(float2*)&C[r0] = v0;
        *(float2*)&C[r1] = v1;
    }
}

// ---------------- fused LSTM layer: cp.async 4-stage tf32 mma + cell epilogue --
// grid = 128 blocks (32-wide r' tiles), 256 threads (8 warps: 2m x 4n).
// Block tile 32(b) x 32(r'). K streams [x@Wih | h@Whh]. 4-stage cp.async.
// RACE-SAFE ping-pong: x read g_xb[l&1] (l>=1)/g_stepin, write g_xb[(l+1)&1];
// h read g_hb[t&1], write g_hb[(t+1)&1]; g_c index-local.
__global__ __launch_bounds__(256) void gates_mma_kernel(int l, int t)
{
    __shared__ float As[4][32][36];
    __shared__ float Ws[4][32][36];
    __shared__ float gsm[32][36];

    const int tid  = threadIdx.x;
    const int warp = tid >> 5, lane = tid & 31;
    const int wm   = warp & 1, wn = warp >> 1;     // 2 m-warps x 4 n-warps
    const int g    = lane >> 2, tig = lane & 3;
    const int n0   = blockIdx.x * 32;

    const float* hp_r = g_hb[t & 1] + (size_t)l*Bz*Hz;
    float*       hp_w = g_hb[(t + 1) & 1] + (size_t)l*Bz*Hz;
    const float* xp_r = g_xb[l & 1];
    float*       xp_w = g_xb[(l + 1) & 1];

    const float* A0; const float* W0; int nc0;
    if (l == 0) { A0 = g_stepin + Ez; W0 = g_wpih + Ez; nc0 = Ez / KC; }
    else        { A0 = xp_r;          W0 = g_wpih + (size_t)l*G4*Hz; nc0 = Hz / KC; }
    const float* A1 = hp_r;
    const float* W1 = g_wphh + (size_t)l*G4*Hz;
    const int total = nc0 + Hz / KC;

    const int lr = tid >> 3, lk = (tid & 7) * 4;   // loader: row 0..31, k4 0..28

    auto issue = [&](int c, int buf) {
        const float* Ap; const float* Wp; int ko;
        if (c < nc0) { Ap = A0; Wp = W0; ko = c * KC; }
        else         { Ap = A1; Wp = W1; ko = (c - nc0) * KC; }
        uint32_t sa = (uint32_t)__cvta_generic_to_shared(&As[buf][lr][lk]);
        uint32_t sw = (uint32_t)__cvta_generic_to_shared(&Ws[buf][lr][lk]);
        cpa16(sa, Ap + (size_t)lr*Hz + ko + lk);
        cpa16(sw, Wp + (size_t)(n0 + lr)*Hz + ko + lk);
    };

    float acc[4] = {0.f, 0.f, 0.f, 0.f};

    // prologue: prefetch 3 stages
#pragma unroll
    for (int s = 0; s < 3; ++s) {
        if (s < total) issue(s, s);
        asm volatile("cp.async.commit_group;");
    }

    for (int kt = 0; kt < total; ++kt) {
        asm volatile("cp.async.wait_group 2;");
        __syncthreads();
        const int buf = kt & 3;
#pragma unroll
        for (int kh = 0; kh < KC; kh += 8) {
            uint32_t a0 = f2tf(As[buf][wm*16 + g    ][kh + tig]);
            uint32_t a1 = f2tf(As[buf][wm*16 + g + 8][kh + tig]);
            uint32_t a2 = f2tf(As[buf][wm*16 + g    ][kh + tig + 4]);
            uint32_t a3 = f2tf(As[buf][wm*16 + g + 8][kh + tig + 4]);
            uint32_t b0 = __float_as_uint(Ws[buf][wn*8 + g][kh + tig]);
            uint32_t b1 = __float_as_uint(Ws[buf][wn*8 + g][kh + tig + 4]);
            asm volatile(
                "mma.sync.aligned.m16n8k8.row.col.f32.tf32.tf32.f32 "
                "{%0,%1,%2,%3}, {%4,%5,%6,%7}, {%8,%9}, {%0,%1,%2,%3};"
                : "+f"(acc[0]), "+f"(acc[1]), "+f"(acc[2]), "+f"(acc[3])
                : "r"(a0), "r"(a1), "r"(a2), "r"(a3), "r"(b0), "r"(b1));
        }
        const int nx = kt + 3;
        if (nx < total) issue(nx, nx & 3);
        asm volatile("cp.async.commit_group;");
    }
    __syncthreads();

    // stage accumulators: rows = b, cols = r' in tile
    {
        const int c = wn*8 + tig*2;
        const int r0 = wm*16 + g;
        gsm[r0    ][c]   = acc[0];
        gsm[r0    ][c+1] = acc[1];
        gsm[r0 + 8][c]   = acc[2];
        gsm[r0 + 8][c+1] = acc[3];
    }
    __syncthreads();

    // cell epilogue: 32 b x 8 j_local = 256 units, one per thread
    {
        const int b  = tid >> 3;
        const int jl = tid & 7;
        const int rl = jl * 4;
        float iv = gsm[b][rl+0];
        float fv = gsm[b][rl+1];
        float gv = gsm[b][rl+2];
        float ov = gsm[b][rl+3];
        if (l == 0) {
            float4 e = *(const float4*)&g_embih[((size_t)t*Bz + b)*G4 + n0 + rl];
            iv += e.x; fv += e.y; gv += e.z; ov += e.w;
        } else {
            float4 pb = *(const float4*)&g_pbias[l*G4 + n0 + rl];
            iv += pb.x; fv += pb.y; gv += pb.z; ov += pb.w;
        }
        float ig = 1.f/(1.f + expf(-iv));
        float fg = 1.f/(1.f + expf(-fv));
        float og = 1.f/(1.f + expf(-ov));
        const int j  = blockIdx.x*8 + jl;
        const int ci = (l*Bz + b)*Hz + j;
        float c2 = fg * g_c[ci] + ig * tanhf(gv);
        g_c[ci] = c2;
        float h2 = og * tanhf(c2);
        hp_w[b*Hz + j] = h2;
        float x = h2 + ((l >= 2) ? g_stepin[b*Hz + j] : 0.f);
        xp_w[b*Hz + j] = x;
        if (l == 3) g_xstore[((size_t)b*TTz + t)*Hz + j] = x;
    }
}

// ---------------- attention scores: grid 128 = (b, s-chunk of 32) --------------
__global__ void attn_scores_kernel(const int* __restrict__ enc_mask)
{
    const int b  = blockIdx.x >> 2;
    const int sc = blockIdx.x & 3;
    const int tid = threadIdx.x;   // 256
    __shared__ float xs[Hz];
    for (int i = tid; i < Hz; i += 256) xs[i] = g_xb[0][b*Hz + i];
    __syncthreads();

    const int warp = tid >> 5, lane = tid & 31;
#pragma unroll
    for (int r = 0; r < 4; ++r) {
        const int s = sc*32 + warp*4 + r;
        const float* m2 = &g_M2[((size_t)b*TSz + s)*Hz];
        float a = 0.f;
        for (int h = lane; h < Hz; h += 32) a += xs[h]*m2[h];
#pragma unroll
        for (int off = 16; off > 0; off >>= 1) a += __shfl_xor_sync(0xffffffffu, a, off);
        if (lane == 0)
            g_scores[b*TSz + s] = (enc_mask[b*TSz + s] > 0) ? a * (1.f/32.f) : -10000.f;
    }
}

// ---------------- attention finish: softmax + ctx + next stepin ----------------
__global__ void attn_finish_kernel(int t, const float* __restrict__ enc_out)
{
    const int b   = blockIdx.x;
    const int tid = threadIdx.x;   // 256
    __shared__ float sc[TSz];
    __shared__ float red[8];

    if (tid < TSz) sc[tid] = g_scores[b*TSz + tid];
    __syncthreads();

    const int warp = tid >> 5, lane = tid & 31;
    float v = (tid < TSz) ? sc[tid] : -1e30f;
    float m = v;
#pragma unroll
    for (int off = 16; off > 0; off >>= 1) m = fmaxf(m, __shfl_xor_sync(0xffffffffu, m, off));
    if (lane == 0) red[warp] = m;
    __syncthreads();
    if (tid == 0) { float mm = red[0]; for (int i = 1; i < 8; ++i) mm = fmaxf(mm, red[i]); red[0] = mm; }
    __syncthreads();
    const float smax = red[0];
    float e = (tid < TSz) ? expf(v - smax) : 0.f;
    float s2 = e;
#pragma unroll
    for (int off = 16; off > 0; off >>= 1) s2 += __shfl_xor_sync(0xffffffffu, s2, off);
    __syncthreads();
    if (lane == 0) red[warp] = s2;
    __syncthreads();
    if (tid == 0) { float ss = 0.f; for (int i = 0; i < 8; ++i) ss += red[i]; red[0] = ss; }
    __syncthreads();
    const float inv = 1.f/red[0];
    if (tid < TSz) sc[tid] = e * inv;
    __syncthreads();

    for (int ei = tid; ei < ENCz; ei += 256) {
        float a = 0.f;
#pragma unroll 4
        for (int s = 0; s < TSz; ++s) a += sc[s]*enc_out[((size_t)b*TSz + s)*ENCz + ei];
        g_stepin[b*Hz + Ez + ei] = a;
    }
    if (t + 1 < TTz) {
        for (int ei = tid; ei < Ez; ei += 256)
            g_stepin[b*Hz + ei] = g_embA[((size_t)(t+1)*Bz + b)*Ez + ei];
    }
}

// ---------------- launch ----------------
static float* symaddr(const void* sym) {
    void* p = nullptr;
    cudaGetSymbolAddress(&p, sym);
    return (float*)p;
}

extern "C" void kernel_launch(void* const* d_in, const int* in_sizes, int n_in,
                              void* d_out, int out_size)
{
    const int*   tgt       = (const int*)  d_in[0];
    const float* enc_out   = (const float*)d_in[2];
    const int*   enc_mask  = (const int*)  d_in[3];
    const float* embedding = (const float*)d_in[4];
    const float* w_ih      = (const float*)d_in[5];
    const float* w_hh      = (const float*)d_in[6];
    const float* b_ih      = (const float*)d_in[7];
    const float* b_hh      = (const float*)d_in[8];
    const float* Wq        = (const float*)d_in[9];
    const float* Wk        = (const float*)d_in[10];
    const float* proj_w    = (const float*)d_in[11];
    const float* proj_b    = (const float*)d_in[12];
    float* out = (float*)d_out;

    float* p_kproj = symaddr(g_kproj);
    float* p_M2    = symaddr(g_M2);
    float* p_WqT   = symaddr(g_WqT);
    float* p_embA  = symaddr(g_embA);
    float* p_embih = symaddr(g_embih);
    float* p_wpih  = symaddr(g_wpih);
    float* p_pbias = symaddr(g_pbias);
    float* p_xst   = symaddr(g_xstore);

    prep_kernel<<<2048, 256>>>(tgt, embedding, w_ih, w_hh, b_ih, b_hh, Wq);

    // kproj = enc_out @ Wk^T : M=4096, N=1024, K=512
    gemm_tf32_kernel<<<dim3(Dz/128, (Bz*TSz)/64), 256>>>(
        enc_out, ENCz, Wk, ENCz, p_kproj, Dz, ENCz, nullptr);

    // embih = embA @ wpih0[:, :512]^T + pbias0 : M=2048, N=4096, K=512
    gemm_tf32_kernel<<<dim3(G4/128, (TTz*Bz)/64), 256>>>(
        p_embA, Ez, p_wpih, Hz, p_embih, G4, Ez, p_pbias);

    // M2 = kproj @ WqT^T : M=4096, N=1024, K=1024
    gemm_tf32_kernel<<<dim3(Hz/128, (Bz*TSz)/64), 256>>>(
        p_kproj, Dz, p_WqT, Dz, p_M2, Hz, Dz, nullptr);

    for (int t = 0; t < TTz; ++t) {
        for (int l = 0; l < Lz; ++l)
            gates_mma_kernel<<<128, 256>>>(l, t);
        if (t + 1 < TTz) {
            attn_scores_kernel<<<128, 256>>>(enc_mask);
            attn_finish_kernel<<<Bz, 256>>>(t, enc_out);
        }
    }

    // vocab projection: out = xstore @ proj_w^T + proj_b
    gemm_tf32_kernel<<<dim3(Vz/128, (Bz*TTz)/64), 256>>>(
        p_xst, Hz, proj_w, Hz, out, Vz, Hz, proj_b);

    (void)in_sizes; (void)n_in; (void)out_size;
}

// round 9
// speedup vs baseline: 3.7001x; 1.0919x over previous
#include <cuda_runtime.h>
#include <math.h>
#include <stdint.h>

// Problem constants (fixed shapes)
#define Bz   32
#define TTz  64
#define TSz  128
#define ENCz 512
#define Ez   512
#define Hz   1024
#define Lz   4
#define Vz   32000
#define Dz   1024
#define G4   4096   // 4*H
#define KC   32     // gates k-chunk

// ---------------- scratch (device globals; no allocation allowed) ----------------
__device__ float g_kproj [Bz*TSz*Dz];    // [ (b*TS+s), d ]  enc_out @ Wk^T
__device__ float g_M2    [Bz*TSz*Hz];    // [ (b*TS+s), h ]  kproj @ Wq
__device__ float g_WqT   [Hz*Dz];        // [h, d] = Wq[d, h]
__device__ float g_embA  [TTz*Bz*Ez];    // [ (t*B+b), e ] gathered embeddings
__device__ float g_embih [TTz*Bz*G4];    // [ (t*B+b), r'] emb @ wpih0[:, :512]^T + bias0
__device__ float g_wpih  [Lz*G4*Hz];     // gate-interleaved w_ih, tf32-rounded
__device__ float g_wphh  [Lz*G4*Hz];     // gate-interleaved w_hh, tf32-rounded
__device__ float g_pbias [Lz*G4];        // permuted b_ih + b_hh
__device__ float g_hb    [2][Lz*Bz*Hz];  // h state, ping-pong on t parity
__device__ float g_c     [Lz*Bz*Hz];     // c state (index-local -> race-safe)
__device__ float g_xb    [2][Bz*Hz];     // layer output, ping-pong on layer parity
__device__ float g_stepin[Bz*Hz];        // [emb_t | ctx]
__device__ float g_xstore[Bz*TTz*Hz];    // [ (b*TT+t), h ] final x, tf32-rounded
__device__ float g_scores[Bz*TSz];       // attention scores (masked, scaled)
__device__ float g_projw [Vz*Hz];        // proj_w, tf32-rounded (no cvt in proj kernel)

__device__ __forceinline__ uint32_t f2tf(float x) {
    uint32_t r; asm("cvt.rna.tf32.f32 %0, %1;" : "=r"(r) : "f"(x)); return r;
}
__device__ __forceinline__ void cpa16(uint32_t saddr, const float* g) {
    asm volatile("cp.async.cg.shared.global [%0], [%1], 16;" :: "r"(saddr), "l"(g));
}

// ---------------- prologue: permute/gather/transpose/round/init ----------------
__global__ void prep_kernel(const int* __restrict__ tgt,
                            const float* __restrict__ embedding,
                            const float* __restrict__ w_ih,
                            const float* __restrict__ w_hh,
                            const float* __restrict__ b_ih,
                            const float* __restrict__ b_hh,
                            const float* __restrict__ Wq,
                            const float* __restrict__ proj_w)
{
    const int stride = gridDim.x * blockDim.x;
    const int base   = blockIdx.x * blockDim.x + threadIdx.x;

    for (int i = base; i < Lz*G4*Hz; i += stride) {
        int k  = i & (Hz-1);
        int rp = (i >> 10) & (G4-1);
        int l  = i >> 22;
        int j  = rp >> 2;
        int g  = rp & 3;
        int src = (l*G4 + g*Hz + j)*Hz + k;
        g_wpih[i] = __uint_as_float(f2tf(w_ih[src]));
        g_wphh[i] = __uint_as_float(f2tf(w_hh[src]));
    }
    for (int i = base; i < Lz*G4; i += stride) {
        int rp = i & (G4-1);
        int l  = i >> 12;
        int j  = rp >> 2, g = rp & 3;
        g_pbias[i] = b_ih[l*G4 + g*Hz + j] + b_hh[l*G4 + g*Hz + j];
    }
    for (int i = base; i < TTz*Bz*Ez; i += stride) {
        int e = i & (Ez-1);
        int m = i >> 9;
        int t = m / Bz, b = m % Bz;
        int tok = tgt[b*TTz + t];
        g_embA[i] = embedding[(size_t)tok*Ez + e];
    }
    for (int i = base; i < Hz*Dz; i += stride) {
        int d = i & (Dz-1);
        int h = i >> 10;
        g_WqT[i] = Wq[d*Hz + h];
    }
    // tf32 pre-round the vocab projection weights
    for (size_t i = base; i < (size_t)Vz*Hz; i += stride)
        g_projw[i] = __uint_as_float(f2tf(proj_w[i]));
    for (int i = base; i < 2*Lz*Bz*Hz; i += stride) ((float*)g_hb)[i] = 0.f;
    for (int i = base; i < Lz*Bz*Hz;   i += stride) g_c[i] = 0.f;
    for (int i = base; i < Bz*Hz; i += stride) {
        int p = i & (Hz-1);
        int b = i >> 10;
        g_stepin[i] = (p < Ez) ? embedding[(size_t)tgt[b*TTz + 0]*Ez + p] : 0.f;
    }
}

// ---------------- generic tf32 mma NT GEMM (+bias) — prologue only -------------
__global__ __launch_bounds__(256) void gemm_tf32_kernel(
    const float* __restrict__ A, int lda,
    const float* __restrict__ W, int ldb,
    float* __restrict__ C, int ldc,
    int K, const float* __restrict__ bias)
{
    __shared__ uint32_t Xs[64][18];
    __shared__ uint32_t Ws[128][18];
    const int m0 = blockIdx.y * 64, n0 = blockIdx.x * 128;
    const int tid = threadIdx.x, warp = tid >> 5, lane = tid & 31;
    const int wm = warp & 3, wn = warp >> 2;
    const int g = lane >> 2, tig = lane & 3;

    float acc[8][4];
#pragma unroll
    for (int i = 0; i < 8; ++i)
#pragma unroll
        for (int j = 0; j < 4; ++j) acc[i][j] = 0.f;

    const int xm = tid >> 2, xk = (tid & 3) * 4;

    for (int k0 = 0; k0 < K; k0 += 16) {
        __syncthreads();
        {
            float4 v = *(const float4*)&A[(size_t)(m0 + xm)*lda + k0 + xk];
            Xs[xm][xk+0] = f2tf(v.x); Xs[xm][xk+1] = f2tf(v.y);
            Xs[xm][xk+2] = f2tf(v.z); Xs[xm][xk+3] = f2tf(v.w);
        }
#pragma unroll
        for (int it = 0; it < 2; ++it) {
            const int n = xm + it*64;
            float4 v = *(const float4*)&W[(size_t)(n0 + n)*ldb + k0 + xk];
            Ws[n][xk+0] = f2tf(v.x); Ws[n][xk+1] = f2tf(v.y);
            Ws[n][xk+2] = f2tf(v.z); Ws[n][xk+3] = f2tf(v.w);
        }
        __syncthreads();
#pragma unroll
        for (int kh = 0; kh < 16; kh += 8) {
            uint32_t a0 = Xs[wm*16 + g    ][kh + tig];
            uint32_t a1 = Xs[wm*16 + g + 8][kh + tig];
            uint32_t a2 = Xs[wm*16 + g    ][kh + tig + 4];
            uint32_t a3 = Xs[wm*16 + g + 8][kh + tig + 4];
#pragma unroll
            for (int nt = 0; nt < 8; ++nt) {
                const uint32_t* wr = &Ws[wn*64 + nt*8 + g][kh];
                uint32_t b0 = wr[tig], b1 = wr[tig + 4];
                asm volatile(
                    "mma.sync.aligned.m16n8k8.row.col.f32.tf32.tf32.f32 "
                    "{%0,%1,%2,%3}, {%4,%5,%6,%7}, {%8,%9}, {%0,%1,%2,%3};"
                    : "+f"(acc[nt][0]), "+f"(acc[nt][1]), "+f"(acc[nt][2]), "+f"(acc[nt][3])
                    : "r"(a0), "r"(a1), "r"(a2), "r"(a3), "r"(b0), "r"(b1));
            }
        }
    }

#pragma unroll
    for (int nt = 0; nt < 8; ++nt) {
        const int n = n0 + wn*64 + nt*8 + tig*2;
        const float b0v = bias ? bias[n]   : 0.f;
        const float b1v = bias ? bias[n+1] : 0.f;
        const size_t r0 = (size_t)(m0 + wm*16 + g) * ldc + n;
        const size_t r1 = r0 + (size_t)8 * ldc;
        float2 v0 = make_float2(acc[nt][0] + b0v, acc[nt][1] + b1v);
        float2 v1 = make_float2(acc[nt][2] + b0v, acc[nt][3] + b1v);
        *(float2*)&C[r0] = v0;
        *(float2*)&C[r1] = v1;
    }
}

// ---------------- vocab projection: cp.async 3-stage tf32 mma ------------------
// C[2048,32000] = X @ W^T + bias. X, W pre-rounded to tf32 (no cvt here).
// Block 64m x 128n; grid (32 m-tiles, 250 n-tiles): m on blockIdx.x so the 32
// CTAs sharing a W n-tile run adjacently -> W served once from DRAM, rest L2.
__global__ __launch_bounds__(256) void proj_pipe_kernel(
    const float* __restrict__ X,
    const float* __restrict__ W,
    const float* __restrict__ bias,
    float* __restrict__ C)
{
    __shared__ uint32_t Xs[3][64][20];
    __shared__ uint32_t Ws[3][128][20];
    const int m0 = blockIdx.x * 64, n0 = blockIdx.y * 128;
    const int tid = threadIdx.x, warp = tid >> 5, lane = tid & 31;
    const int wm = warp & 3, wn = warp >> 2;
    const int g = lane >> 2, tig = lane & 3;

    const int lr = tid >> 2, lk = (tid & 3) * 4;   // loader row 0..63, k 0..12

    auto issue = [&](int c, int buf) {
        const int ko = c * 16;
        cpa16((uint32_t)__cvta_generic_to_shared(&Xs[buf][lr][lk]),
              X + (size_t)(m0 + lr)*Hz + ko + lk);
        cpa16((uint32_t)__cvta_generic_to_shared(&Ws[buf][lr][lk]),
              W + (size_t)(n0 + lr)*Hz + ko + lk);
        cpa16((uint32_t)__cvta_generic_to_shared(&Ws[buf][lr + 64][lk]),
              W + (size_t)(n0 + lr + 64)*Hz + ko + lk);
    };

    float acc[8][4];
#pragma unroll
    for (int i = 0; i < 8; ++i)
#pragma unroll
        for (int j = 0; j < 4; ++j) acc[i][j] = 0.f;

    const int total = Hz / 16;   // 64 chunks
    issue(0, 0); asm volatile("cp.async.commit_group;");
    issue(1, 1); asm volatile("cp.async.commit_group;");

    for (int kt = 0; kt < total; ++kt) {
        asm volatile("cp.async.wait_group 1;");
        __syncthreads();
        const int buf = kt % 3;
#pragma unroll
        for (int kh = 0; kh < 16; kh += 8) {
            uint32_t a0 = Xs[buf][wm*16 + g    ][kh + tig];
            uint32_t a1 = Xs[buf][wm*16 + g + 8][kh + tig];
            uint32_t a2 = Xs[buf][wm*16 + g    ][kh + tig + 4];
            uint32_t a3 = Xs[buf][wm*16 + g + 8][kh + tig + 4];
#pragma unroll
            for (int nt = 0; nt < 8; ++nt) {
                const uint32_t* wr = &Ws[buf][wn*64 + nt*8 + g][kh];
                uint32_t b0 = wr[tig], b1 = wr[tig + 4];
                asm volatile(
                    "mma.sync.aligned.m16n8k8.row.col.f32.tf32.tf32.f32 "
                    "{%0,%1,%2,%3}, {%4,%5,%6,%7}, {%8,%9}, {%0,%1,%2,%3};"
                    : "+f"(acc[nt][0]), "+f"(acc[nt][1]), "+f"(acc[nt][2]), "+f"(acc[nt][3])
                    : "r"(a0), "r"(a1), "r"(a2), "r"(a3), "r"(b0), "r"(b1));
            }
        }
        const int nx = kt + 2;
        if (nx < total) issue(nx, nx % 3);
        asm volatile("cp.async.commit_group;");
    }

#pragma unroll
    for (int nt = 0; nt < 8; ++nt) {
        const int n = n0 + wn*64 + nt*8 + tig*2;
        const float b0v = bias[n], b1v = bias[n+1];
        const size_t r0 = (size_t)(m0 + wm*16 + g) * Vz + n;
        const size_t r1 = r0 + (size_t)8 * Vz;
        float2 v0 = make_float2(acc[nt][0] + b0v, acc[nt][1] + b1v);
        float2 v1 = make_float2(acc[nt][2] + b0v, acc[nt][3] + b1v);
        *(float2*)&C[r0] = v0;
        *(float2*)&C[r1] = v1;
    }
}

// ---------------- fused LSTM layer: cp.async 4-stage tf32 mma + cell epilogue --
// grid = 128 blocks (32-wide r' tiles), 256 threads (8 warps: 2m x 4n).
// RACE-SAFE ping-pong: x read g_xb[l&1] (l>=1)/g_stepin, write g_xb[(l+1)&1];
// h read g_hb[t&1], write g_hb[(t+1)&1]; g_c index-local.
__global__ __launch_bounds__(256) void gates_mma_kernel(int l, int t)
{
    __shared__ float As[4][32][36];
    __shared__ float Ws[4][32][36];
    __shared__ float gsm[32][36];

    const int tid  = threadIdx.x;
    const int warp = tid >> 5, lane = tid & 31;
    const int wm   = warp & 1, wn = warp >> 1;
    const int g    = lane >> 2, tig = lane & 3;
    const int n0   = blockIdx.x * 32;

    const float* hp_r = g_hb[t & 1] + (size_t)l*Bz*Hz;
    float*       hp_w = g_hb[(t + 1) & 1] + (size_t)l*Bz*Hz;
    const float* xp_r = g_xb[l & 1];
    float*       xp_w = g_xb[(l + 1) & 1];

    const float* A0; const float* W0; int nc0;
    if (l == 0) { A0 = g_stepin + Ez; W0 = g_wpih + Ez; nc0 = Ez / KC; }
    else        { A0 = xp_r;          W0 = g_wpih + (size_t)l*G4*Hz; nc0 = Hz / KC; }
    const float* A1 = hp_r;
    const float* W1 = g_wphh + (size_t)l*G4*Hz;
    const int total = nc0 + Hz / KC;

    const int lr = tid >> 3, lk = (tid & 7) * 4;

    auto issue = [&](int c, int buf) {
        const float* Ap; const float* Wp; int ko;
        if (c < nc0) { Ap = A0; Wp = W0; ko = c * KC; }
        else         { Ap = A1; Wp = W1; ko = (c - nc0) * KC; }
        uint32_t sa = (uint32_t)__cvta_generic_to_shared(&As[buf][lr][lk]);
        uint32_t sw = (uint32_t)__cvta_generic_to_shared(&Ws[buf][lr][lk]);
        cpa16(sa, Ap + (size_t)lr*Hz + ko + lk);
        cpa16(sw, Wp + (size_t)(n0 + lr)*Hz + ko + lk);
    };

    float acc[4] = {0.f, 0.f, 0.f, 0.f};

#pragma unroll
    for (int s = 0; s < 3; ++s) {
        if (s < total) issue(s, s);
        asm volatile("cp.async.commit_group;");
    }

    for (int kt = 0; kt < total; ++kt) {
        asm volatile("cp.async.wait_group 2;");
        __syncthreads();
        const int buf = kt & 3;
#pragma unroll
        for (int kh = 0; kh < KC; kh += 8) {
            uint32_t a0 = f2tf(As[buf][wm*16 + g    ][kh + tig]);
            uint32_t a1 = f2tf(As[buf][wm*16 + g + 8][kh + tig]);
            uint32_t a2 = f2tf(As[buf][wm*16 + g    ][kh + tig + 4]);
            uint32_t a3 = f2tf(As[buf][wm*16 + g + 8][kh + tig + 4]);
            uint32_t b0 = __float_as_uint(Ws[buf][wn*8 + g][kh + tig]);
            uint32_t b1 = __float_as_uint(Ws[buf][wn*8 + g][kh + tig + 4]);
            asm volatile(
                "mma.sync.aligned.m16n8k8.row.col.f32.tf32.tf32.f32 "
                "{%0,%1,%2,%3}, {%4,%5,%6,%7}, {%8,%9}, {%0,%1,%2,%3};"
                : "+f"(acc[0]), "+f"(acc[1]), "+f"(acc[2]), "+f"(acc[3])
                : "r"(a0), "r"(a1), "r"(a2), "r"(a3), "r"(b0), "r"(b1));
        }
        const int nx = kt + 3;
        if (nx < total) issue(nx, nx & 3);
        asm volatile("cp.async.commit_group;");
    }
    __syncthreads();

    {
        const int c = wn*8 + tig*2;
        const int r0 = wm*16 + g;
        gsm[r0    ][c]   = acc[0];
        gsm[r0    ][c+1] = acc[1];
        gsm[r0 + 8][c]   = acc[2];
        gsm[r0 + 8][c+1] = acc[3];
    }
    __syncthreads();

    {
        const int b  = tid >> 3;
        const int jl = tid & 7;
        const int rl = jl * 4;
        float iv = gsm[b][rl+0];
        float fv = gsm[b][rl+1];
        float gv = gsm[b][rl+2];
        float ov = gsm[b][rl+3];
        if (l == 0) {
            float4 e = *(const float4*)&g_embih[((size_t)t*Bz + b)*G4 + n0 + rl];
            iv += e.x; fv += e.y; gv += e.z; ov += e.w;
        } else {
            float4 pb = *(const float4*)&g_pbias[l*G4 + n0 + rl];
            iv += pb.x; fv += pb.y; gv += pb.z; ov += pb.w;
        }
        float ig = 1.f/(1.f + expf(-iv));
        float fg = 1.f/(1.f + expf(-fv));
        float og = 1.f/(1.f + expf(-ov));
        const int j  = blockIdx.x*8 + jl;
        const int ci = (l*Bz + b)*Hz + j;
        float c2 = fg * g_c[ci] + ig * tanhf(gv);
        g_c[ci] = c2;
        float h2 = og * tanhf(c2);
        hp_w[b*Hz + j] = h2;
        float x = h2 + ((l >= 2) ? g_stepin[b*Hz + j] : 0.f);
        xp_w[b*Hz + j] = x;
        if (l == 3) g_xstore[((size_t)b*TTz + t)*Hz + j] = __uint_as_float(f2tf(x));
    }
}

// ---------------- attention scores: grid 128 = (b, s-chunk of 32) --------------
__global__ void attn_scores_kernel(const int* __restrict__ enc_mask)
{
    const int b  = blockIdx.x >> 2;
    const int sc = blockIdx.x & 3;
    const int tid = threadIdx.x;   // 256
    __shared__ float xs[Hz];
    for (int i = tid; i < Hz; i += 256) xs[i] = g_xb[0][b*Hz + i];
    __syncthreads();

    const int warp = tid >> 5, lane = tid & 31;
#pragma unroll
    for (int r = 0; r < 4; ++r) {
        const int s = sc*32 + warp*4 + r;
        const float* m2 = &g_M2[((size_t)b*TSz + s)*Hz];
        float a = 0.f;
        for (int h = lane; h < Hz; h += 32) a += xs[h]*m2[h];
#pragma unroll
        for (int off = 16; off > 0; off >>= 1) a += __shfl_xor_sync(0xffffffffu, a, off);
        if (lane == 0)
            g_scores[b*TSz + s] = (enc_mask[b*TSz + s] > 0) ? a * (1.f/32.f) : -10000.f;
    }
}

// ---------------- attention finish: softmax + ctx + next stepin ----------------
__global__ void attn_finish_kernel(int t, const float* __restrict__ enc_out)
{
    const int b   = blockIdx.x;
    const int tid = threadIdx.x;   // 256
    __shared__ float sc[TSz];
    __shared__ float red[8];

    if (tid < TSz) sc[tid] = g_scores[b*TSz + tid];
    __syncthreads();

    const int warp = tid >> 5, lane = tid & 31;
    float v = (tid < TSz) ? sc[tid] : -1e30f;
    float m = v;
#pragma unroll
    for (int off = 16; off > 0; off >>= 1) m = fmaxf(m, __shfl_xor_sync(0xffffffffu, m, off));
    if (lane == 0) red[warp] = m;
    __syncthreads();
    if (tid == 0) { float mm = red[0]; for (int i = 1; i < 8; ++i) mm = fmaxf(mm, red[i]); red[0] = mm; }
    __syncthreads();
    const float smax = red[0];
    float e = (tid < TSz) ? expf(v - smax) : 0.f;
    float s2 = e;
#pragma unroll
    for (int off = 16; off > 0; off >>= 1) s2 += __shfl_xor_sync(0xffffffffu, s2, off);
    __syncthreads();
    if (lane == 0) red[warp] = s2;
    __syncthreads();
    if (tid == 0) { float ss = 0.f; for (int i = 0; i < 8; ++i) ss += red[i]; red[0] = ss; }
    __syncthreads();
    const float inv = 1.f/red[0];
    if (tid < TSz) sc[tid] = e * inv;
    __syncthreads();

    for (int ei = tid; ei < ENCz; ei += 256) {
        float a = 0.f;
#pragma unroll 4
        for (int s = 0; s < TSz; ++s) a += sc[s]*enc_out[((size_t)b*TSz + s)*ENCz + ei];
        g_stepin[b*Hz + Ez + ei] = a;
    }
    if (t + 1 < TTz) {
        for (int ei = tid; ei < Ez; ei += 256)
            g_stepin[b*Hz + ei] = g_embA[((size_t)(t+1)*Bz + b)*Ez + ei];
    }
}

// ---------------- launch ----------------
static float* symaddr(const void* sym) {
    void* p = nullptr;
    cudaGetSymbolAddress(&p, sym);
    return (float*)p;
}

extern "C" void kernel_launch(void* const* d_in, const int* in_sizes, int n_in,
                              void* d_out, int out_size)
{
    const int*   tgt       = (const int*)  d_in[0];
    const float* enc_out   = (const float*)d_in[2];
    const int*   enc_mask  = (const int*)  d_in[3];
    const float* embedding = (const float*)d_in[4];
    const float* w_ih      = (const float*)d_in[5];
    const float* w_hh      = (const float*)d_in[6];
    const float* b_ih      = (const float*)d_in[7];
    const float* b_hh      = (const float*)d_in[8];
    const float* Wq        = (const float*)d_in[9];
    const float* Wk        = (const float*)d_in[10];
    const float* proj_w    = (const float*)d_in[11];
    const float* proj_b    = (const float*)d_in[12];
    float* out = (float*)d_out;

    float* p_kproj = symaddr(g_kproj);
    float* p_M2    = symaddr(g_M2);
    float* p_WqT   = symaddr(g_WqT);
    float* p_embA  = symaddr(g_embA);
    float* p_embih = symaddr(g_embih);
    float* p_wpih  = symaddr(g_wpih);
    float* p_pbias = symaddr(g_pbias);
    float* p_xst   = symaddr(g_xstore);
    float* p_projw = symaddr(g_projw);

    prep_kernel<<<2048, 256>>>(tgt, embedding, w_ih, w_hh, b_ih, b_hh, Wq, proj_w);

    // kproj = enc_out @ Wk^T : M=4096, N=1024, K=512
    gemm_tf32_kernel<<<dim3(Dz/128, (Bz*TSz)/64), 256>>>(
        enc_out, ENCz, Wk, ENCz, p_kproj, Dz, ENCz, nullptr);

    // embih = embA @ wpih0[:, :512]^T + pbias0 : M=2048, N=4096, K=512
    gemm_tf32_kernel<<<dim3(G4/128, (TTz*Bz)/64), 256>>>(
        p_embA, Ez, p_wpih, Hz, p_embih, G4, Ez, p_pbias);

    // M2 = kproj @ WqT^T : M=4096, N=1024, K=1024
    gemm_tf32_kernel<<<dim3(Hz/128, (Bz*TSz)/64), 256>>>(
        p_kproj, Dz, p_WqT, Dz, p_M2, Hz, Dz, nullptr);

    for (int t = 0; t < TTz; ++t) {
        for (int l = 0; l < Lz; ++l)
            gates_mma_kernel<<<128, 256>>>(l, t);
        if (t + 1 < TTz) {
            attn_scores_kernel<<<128, 256>>>(enc_mask);
            attn_finish_kernel<<<Bz, 256>>>(t, enc_out);
        }
    }

    // vocab projection: out = xstore @ projw^T + proj_b (pipelined, m-major grid)
    proj_pipe_kernel<<<dim3((Bz*TTz)/64, Vz/128), 256>>>(p_xst, p_projw, proj_b, out);

    (void)in_sizes; (void)n_in; (void)out_size;
}